// round 7
// baseline (speedup 1.0000x reference)
#include <cuda_runtime.h>
#include <math.h>

// Problem constants
#define BB   2
#define SS   2048
#define DD   2048
#define NH   16
#define NKV  4
#define HD   128
#define EHEADS (NH + 2*NKV)          // 24
#define QKVE (EHEADS * HD)           // 3072

// ---------------- scratch (device globals; no allocation allowed) ----------
__device__ __align__(16) float g_qkv[(size_t)BB * SS * QKVE];     // [4096][3072]
__device__ __align__(16) float g_qt [(size_t)BB * NH  * HD * SS]; // [B][NH][HD][S]
__device__ __align__(16) float g_kt [(size_t)BB * NKV * HD * SS]; // [B][NKV][HD][S]
__device__ __align__(16) float g_y  [(size_t)BB * SS * DD];       // [4096][2048]

// ---------------- packed f32x2 helpers -------------------------------------
__device__ __forceinline__ unsigned long long pack2(float x) {
    unsigned long long r;
    asm("mov.b64 %0, {%1, %1};" : "=l"(r) : "f"(x));
    return r;
}
__device__ __forceinline__ void fma2(unsigned long long& c,
                                     unsigned long long a,
                                     unsigned long long b) {
    asm("fma.rn.f32x2 %0, %1, %2, %0;" : "+l"(c) : "l"(a), "l"(b));
}
__device__ __forceinline__ void mul2(unsigned long long& c, unsigned long long a) {
    asm("mul.rn.f32x2 %0, %0, %1;" : "+l"(c) : "l"(a));
}
__device__ __forceinline__ float2 unpack2(unsigned long long v) {
    float2 r;
    asm("mov.b64 {%0, %1}, %2;" : "=f"(r.x), "=f"(r.y) : "l"(v));
    return r;
}
__device__ __forceinline__ float ex2f(float x) {
    float y;
    asm("ex2.approx.ftz.f32 %0, %1;" : "=f"(y) : "f"(x));
    return y;
}

// ---------------- GEMM: C[M,N] = A[M,K] * B[N,K]^T  (both K-major) ----------
#define GBM 128
#define GBN 128
#define GBK 16
#define GAS (GBM + 4)   // padded row stride (floats)

__global__ void __launch_bounds__(256, 2) gemm_nt(const float* __restrict__ A,
                                                  const float* __restrict__ B,
                                                  float* __restrict__ C,
                                                  int M, int N, int K)
{
    __shared__ __align__(16) float As[2][GBK * GAS];
    __shared__ __align__(16) float Bs[2][GBK * GAS];

    const int tid  = threadIdx.x;
    const int bm   = blockIdx.y * GBM;
    const int bn   = blockIdx.x * GBN;
    const int lrow = tid >> 2;          // 0..63
    const int lk4  = (tid & 3) << 2;    // 0,4,8,12

    const float* Ap = A + (size_t)(bm + lrow) * K + lk4;
    const float* Bp = B + (size_t)(bn + lrow) * K + lk4;
    const size_t rowoff = (size_t)64 * K;

    unsigned long long acc[8][4];
    #pragma unroll
    for (int i = 0; i < 8; i++)
        #pragma unroll
        for (int j = 0; j < 4; j++)
            acc[i][j] = 0ull;

    const int ty = tid >> 4, tx = tid & 15;
    const int nk = K / GBK;

    float4 a0 = *(const float4*)Ap;
    float4 a1 = *(const float4*)(Ap + rowoff);
    float4 b0 = *(const float4*)Bp;
    float4 b1 = *(const float4*)(Bp + rowoff);

    {
        float* Aw = As[0]; float* Bw = Bs[0];
        Aw[(lk4+0)*GAS + lrow]      = a0.x;
        Aw[(lk4+1)*GAS + lrow]      = a0.y;
        Aw[(lk4+2)*GAS + lrow]      = a0.z;
        Aw[(lk4+3)*GAS + lrow]      = a0.w;
        Aw[(lk4+0)*GAS + lrow + 64] = a1.x;
        Aw[(lk4+1)*GAS + lrow + 64] = a1.y;
        Aw[(lk4+2)*GAS + lrow + 64] = a1.z;
        Aw[(lk4+3)*GAS + lrow + 64] = a1.w;
        Bw[(lk4+0)*GAS + lrow]      = b0.x;
        Bw[(lk4+1)*GAS + lrow]      = b0.y;
        Bw[(lk4+2)*GAS + lrow]      = b0.z;
        Bw[(lk4+3)*GAS + lrow]      = b0.w;
        Bw[(lk4+0)*GAS + lrow + 64] = b1.x;
        Bw[(lk4+1)*GAS + lrow + 64] = b1.y;
        Bw[(lk4+2)*GAS + lrow + 64] = b1.z;
        Bw[(lk4+3)*GAS + lrow + 64] = b1.w;
    }
    __syncthreads();

    for (int t = 0; t < nk; ++t) {
        const int cur = t & 1;
        if (t + 1 < nk) {
            Ap += GBK; Bp += GBK;
            a0 = *(const float4*)Ap;
            a1 = *(const float4*)(Ap + rowoff);
            b0 = *(const float4*)Bp;
            b1 = *(const float4*)(Bp + rowoff);
        }

        const float* Ar = As[cur];
        const float* Br = Bs[cur];
        #pragma unroll
        for (int k = 0; k < GBK; ++k) {
            const float* arow = &Ar[k*GAS + ty*8];
            float4 af0 = *(const float4*)(arow);
            float4 af1 = *(const float4*)(arow + 4);
            ulonglong2 bl0 = *(const ulonglong2*)&Br[k*GAS + tx*4];
            ulonglong2 bl1 = *(const ulonglong2*)&Br[k*GAS + 64 + tx*4];

            unsigned long long av[8];
            av[0] = pack2(af0.x); av[1] = pack2(af0.y);
            av[2] = pack2(af0.z); av[3] = pack2(af0.w);
            av[4] = pack2(af1.x); av[5] = pack2(af1.y);
            av[6] = pack2(af1.z); av[7] = pack2(af1.w);
            unsigned long long bv[4] = {bl0.x, bl0.y, bl1.x, bl1.y};

            #pragma unroll
            for (int i = 0; i < 8; i++)
                #pragma unroll
                for (int jp = 0; jp < 4; jp++)
                    fma2(acc[i][jp], av[i], bv[jp]);
        }

        if (t + 1 < nk) {
            const int nxt = (t + 1) & 1;
            float* Aw = As[nxt]; float* Bw = Bs[nxt];
            Aw[(lk4+0)*GAS + lrow]      = a0.x;
            Aw[(lk4+1)*GAS + lrow]      = a0.y;
            Aw[(lk4+2)*GAS + lrow]      = a0.z;
            Aw[(lk4+3)*GAS + lrow]      = a0.w;
            Aw[(lk4+0)*GAS + lrow + 64] = a1.x;
            Aw[(lk4+1)*GAS + lrow + 64] = a1.y;
            Aw[(lk4+2)*GAS + lrow + 64] = a1.z;
            Aw[(lk4+3)*GAS + lrow + 64] = a1.w;
            Bw[(lk4+0)*GAS + lrow]      = b0.x;
            Bw[(lk4+1)*GAS + lrow]      = b0.y;
            Bw[(lk4+2)*GAS + lrow]      = b0.z;
            Bw[(lk4+3)*GAS + lrow]      = b0.w;
            Bw[(lk4+0)*GAS + lrow + 64] = b1.x;
            Bw[(lk4+1)*GAS + lrow + 64] = b1.y;
            Bw[(lk4+2)*GAS + lrow + 64] = b1.z;
            Bw[(lk4+3)*GAS + lrow + 64] = b1.w;
        }
        __syncthreads();
    }

    #pragma unroll
    for (int i = 0; i < 8; i++) {
        float2 c0 = unpack2(acc[i][0]);
        float2 c1 = unpack2(acc[i][1]);
        float2 c2 = unpack2(acc[i][2]);
        float2 c3 = unpack2(acc[i][3]);
        float* cp = C + (size_t)(bm + ty*8 + i) * N + bn;
        *(float4*)(cp + tx*4)      = make_float4(c0.x, c0.y, c1.x, c1.y);
        *(float4*)(cp + 64 + tx*4) = make_float4(c2.x, c2.y, c3.x, c3.y);
    }
}

// ---------------- RMSNorm + RoPE + transpose to [B,H][HD][S] ----------------
#define QSCALE 0.12751943f   // (1/sqrt(128)) * log2(e)
__global__ void __launch_bounds__(256) norm_rope_t(const float* __restrict__ qkv,
                                                   const float* __restrict__ freqs,
                                                   const float* __restrict__ qw,
                                                   const float* __restrict__ kw,
                                                   float* __restrict__ qt,
                                                   float* __restrict__ kt)
{
    __shared__ float st[128 * 33];
    const int s0   = blockIdx.x * 32;
    const int h    = blockIdx.y;
    const int b    = blockIdx.z;
    const int w    = threadIdx.x >> 5;
    const int lane = threadIdx.x & 31;
    const bool isq = (h < NH);
    const float fold = isq ? QSCALE : 1.0f;
    const float* wn  = isq ? qw : kw;
    const float4 wv  = *(const float4*)(wn + lane*4);

    #pragma unroll
    for (int ii = 0; ii < 4; ii++) {
        const int sl = w*4 + ii;
        const int s  = s0 + sl;
        const float* src = qkv + ((size_t)(b*SS + s)) * QKVE + h * HD;
        float4 v = *(const float4*)(src + lane*4);
        float ssum = v.x*v.x + v.y*v.y + v.z*v.z + v.w*v.w;
        #pragma unroll
        for (int off = 16; off >= 1; off >>= 1)
            ssum += __shfl_xor_sync(0xffffffffu, ssum, off);
        float inv = rsqrtf(ssum * (1.0f / HD) + 1e-6f) * fold;
        float x0 = v.x * inv * wv.x;
        float x1 = v.y * inv * wv.y;
        float x2 = v.z * inv * wv.z;
        float x3 = v.w * inv * wv.w;
        float4 f = *(const float4*)(freqs + (size_t)s*128 + lane*4);
        st[(lane*4+0)*33 + sl] = x0*f.x - x1*f.y;
        st[(lane*4+1)*33 + sl] = x1*f.x + x0*f.y;
        st[(lane*4+2)*33 + sl] = x2*f.z - x3*f.w;
        st[(lane*4+3)*33 + sl] = x3*f.z + x2*f.w;
    }
    __syncthreads();

    float* dst = isq ? (qt + ((size_t)(b*NH  + h))      * HD * SS)
                     : (kt + ((size_t)(b*NKV + h - NH)) * HD * SS);
    #pragma unroll
    for (int it = 0; it < 4; it++) {
        int lin = threadIdx.x + it*256;
        int d   = lin >> 3;
        int sl4 = (lin & 7) << 2;
        float4 o = make_float4(st[d*33 + sl4 + 0], st[d*33 + sl4 + 1],
                               st[d*33 + sl4 + 2], st[d*33 + sl4 + 3]);
        *(float4*)(dst + (size_t)d*SS + s0 + sl4) = o;
    }
}

// ---------------- Flash attention (causal, GQA), BM=64 ----------------------
// Ps aliases the (dead-after-QK) Ks region -> smem = 96 KB -> 2 CTAs/SM sure.
#define QKS 64    // stride for Qs/Ks [d][r]/[d][c]
#define FVS 128   // d-stride for Vs [kk][d]
#define PRS 68    // r-stride for Ps [c][r] (multiple of 4; fits in Ks region: 64*68 <= 128*64)
#define FLASH_SMEM ((128*QKS + 128*QKS + 64*FVS) * 4)   // 98304 B

__global__ void __launch_bounds__(256, 2) flash_kernel(const float* __restrict__ Qt,
                                                       const float* __restrict__ Kt,
                                                       const float* __restrict__ qkv,
                                                       float* __restrict__ Y)
{
    extern __shared__ __align__(16) float sm[];
    float* Qs = sm;                    // [d][r]  128 x 64 (pre-scaled)
    float* Ks = Qs + 128*QKS;          // [d][c]  128 x 64
    float* Vs = Ks + 128*QKS;          // [kk][d]  64 x 128
    float* Ps = Ks;                    // [c][r]   64 x 68  (aliases Ks)

    const int tid = threadIdx.x;
    const int qb  = gridDim.x - 1 - blockIdx.x;   // long blocks first
    const int h   = blockIdx.y;
    const int b   = blockIdx.z;
    const int q0  = qb * 64;

    const float* qsrc = Qt  + ((size_t)(b*NH  + h)        * HD) * SS + q0;
    const float* ksrc = Kt  + ((size_t)(b*NKV + (h >> 2)) * HD) * SS;
    const float* vsrc = qkv + ((size_t)b*SS) * QKVE + (NH + NKV + (h >> 2)) * HD;

    // Q tile: transposed in global, direct coalesced copy
    #pragma unroll
    for (int it = 0; it < 8; it++) {
        int lin = tid + it*256;
        int d   = lin >> 4;
        int rr  = (lin & 15) << 2;
        *(float4*)&Qs[d*QKS + rr] = *(const float4*)(qsrc + (size_t)d*SS + rr);
    }

    const int ty = tid >> 4, tx = tid & 15;
    unsigned long long o2[4][4];
    float m[4], l[4];
    #pragma unroll
    for (int i = 0; i < 4; i++) {
        m[i] = -1e30f; l[i] = 0.f;
        #pragma unroll
        for (int j = 0; j < 4; j++) o2[i][j] = 0ull;
    }
    __syncthreads();

    const int nkb = qb + 1;
    for (int kb = 0; kb < nkb; ++kb) {
        const int k0 = kb * 64;
        #pragma unroll
        for (int it = 0; it < 8; it++) {
            int lin = tid + it*256;
            int d   = lin >> 4;
            int c4  = (lin & 15) << 2;
            *(float4*)&Ks[d*QKS + c4] = *(const float4*)(ksrc + (size_t)d*SS + k0 + c4);
            int r   = lin >> 5;
            int d4  = (lin & 31) << 2;
            *(float4*)&Vs[r*FVS + d4] = *(const float4*)(vsrc + (size_t)(k0 + r)*QKVE + d4);
        }
        __syncthreads();

        unsigned long long acc0[4], acc1[4];
        #pragma unroll
        for (int j = 0; j < 4; j++) { acc0[j] = 0ull; acc1[j] = 0ull; }

        #pragma unroll 2
        for (int d = 0; d < 128; ++d) {
            ulonglong2 qp = *(const ulonglong2*)&Qs[d*QKS + ty*4];
            float4 kk4 = *(const float4*)&Ks[d*QKS + tx*4];
            unsigned long long b0 = pack2(kk4.x), b1 = pack2(kk4.y);
            unsigned long long b2 = pack2(kk4.z), b3 = pack2(kk4.w);
            fma2(acc0[0], qp.x, b0); fma2(acc1[0], qp.y, b0);
            fma2(acc0[1], qp.x, b1); fma2(acc1[1], qp.y, b1);
            fma2(acc0[2], qp.x, b2); fma2(acc1[2], qp.y, b2);
            fma2(acc0[3], qp.x, b3); fma2(acc1[3], qp.y, b3);
        }
        __syncthreads();   // all QK reads of Ks done before Ps (alias) is written

        float s[4][4];
        #pragma unroll
        for (int j = 0; j < 4; j++) {
            float2 p01 = unpack2(acc0[j]);
            float2 p23 = unpack2(acc1[j]);
            s[0][j] = p01.x; s[1][j] = p01.y;
            s[2][j] = p23.x; s[3][j] = p23.y;
        }

        if (kb == qb) {   // diagonal tile: causal mask
            #pragma unroll
            for (int i = 0; i < 4; i++)
                #pragma unroll
                for (int j = 0; j < 4; j++)
                    if (k0 + tx*4 + j > q0 + ty*4 + i) s[i][j] = -1e30f;
        }

        // online softmax in log2 domain (Q pre-scaled by scale*log2e)
        #pragma unroll
        for (int i = 0; i < 4; i++) {
            float mx = fmaxf(fmaxf(s[i][0], s[i][1]), fmaxf(s[i][2], s[i][3]));
            #pragma unroll
            for (int off = 8; off >= 1; off >>= 1)
                mx = fmaxf(mx, __shfl_xor_sync(0xffffffffu, mx, off, 16));
            float mn   = fmaxf(m[i], mx);
            float corr = ex2f(m[i] - mn);
            m[i] = mn;
            float rs = 0.f;
            #pragma unroll
            for (int j = 0; j < 4; j++) {
                float p = ex2f(s[i][j] - mn);
                s[i][j] = p;
                rs += p;
            }
            #pragma unroll
            for (int off = 8; off >= 1; off >>= 1)
                rs += __shfl_xor_sync(0xffffffffu, rs, off, 16);
            l[i] = l[i] * corr + rs;
            unsigned long long c2 = pack2(corr);
            #pragma unroll
            for (int j = 0; j < 4; j++) mul2(o2[i][j], c2);
        }

        // store P transposed [c][r] into the Ks region
        #pragma unroll
        for (int j = 0; j < 4; j++) {
            *(float4*)&Ps[(tx*4 + j)*PRS + ty*4]
                = make_float4(s[0][j], s[1][j], s[2][j], s[3][j]);
        }
        __syncthreads();

        // O += P * V
        #pragma unroll 2
        for (int kk = 0; kk < 64; ++kk) {
            float4 pv = *(const float4*)&Ps[kk*PRS + ty*4];
            unsigned long long p0 = pack2(pv.x), p1 = pack2(pv.y);
            unsigned long long p2 = pack2(pv.z), p3 = pack2(pv.w);
            ulonglong2 va = *(const ulonglong2*)&Vs[kk*FVS + tx*4];
            ulonglong2 vb = *(const ulonglong2*)&Vs[kk*FVS + 64 + tx*4];
            fma2(o2[0][0], p0, va.x); fma2(o2[0][1], p0, va.y);
            fma2(o2[0][2], p0, vb.x); fma2(o2[0][3], p0, vb.y);
            fma2(o2[1][0], p1, va.x); fma2(o2[1][1], p1, va.y);
            fma2(o2[1][2], p1, vb.x); fma2(o2[1][3], p1, vb.y);
            fma2(o2[2][0], p2, va.x); fma2(o2[2][1], p2, va.y);
            fma2(o2[2][2], p2, vb.x); fma2(o2[2][3], p2, vb.y);
            fma2(o2[3][0], p3, va.x); fma2(o2[3][1], p3, va.y);
            fma2(o2[3][2], p3, vb.x); fma2(o2[3][3], p3, vb.y);
        }
        __syncthreads();
    }

    #pragma unroll
    for (int i = 0; i < 4; i++) {
        float inv = 1.0f / l[i];
        int row = q0 + ty*4 + i;
        float* yp = Y + ((size_t)(b*SS + row)) * DD + h*HD;
        float2 c0 = unpack2(o2[i][0]);
        float2 c1 = unpack2(o2[i][1]);
        float2 c2 = unpack2(o2[i][2]);
        float2 c3 = unpack2(o2[i][3]);
        *(float4*)(yp + tx*4)      = make_float4(c0.x*inv, c0.y*inv, c1.x*inv, c1.y*inv);
        *(float4*)(yp + 64 + tx*4) = make_float4(c2.x*inv, c2.y*inv, c3.x*inv, c3.y*inv);
    }
}

// ---------------- launch ----------------------------------------------------
extern "C" void kernel_launch(void* const* d_in, const int* in_sizes, int n_in,
                              void* d_out, int out_size)
{
    const float* x     = (const float*)d_in[0];
    const float* freqs = (const float*)d_in[1];
    const float* wqkv  = (const float*)d_in[2];
    const float* wo    = (const float*)d_in[3];
    const float* qw    = (const float*)d_in[4];
    const float* kw    = (const float*)d_in[5];
    float* out = (float*)d_out;

    float *p_qkv, *p_qt, *p_kt, *p_y;
    cudaGetSymbolAddress((void**)&p_qkv, g_qkv);
    cudaGetSymbolAddress((void**)&p_qt,  g_qt);
    cudaGetSymbolAddress((void**)&p_kt,  g_kt);
    cudaGetSymbolAddress((void**)&p_y,   g_y);

    // 1) QKV projection: [4096,3072] = x[4096,2048] * wqkv[3072,2048]^T
    gemm_nt<<<dim3(QKVE/GBN, (BB*SS)/GBM), 256>>>(x, wqkv, p_qkv,
                                                  BB*SS, QKVE, DD);

    // 2) RMSNorm + RoPE + transpose (Q pre-scaled); V stays in g_qkv
    norm_rope_t<<<dim3(SS/32, NH + NKV, BB), 256>>>(p_qkv, freqs, qw, kw,
                                                    p_qt, p_kt);

    // 3) Flash attention (causal, GQA), BM=64, 96KB smem -> 2 CTAs/SM
    cudaFuncSetAttribute(flash_kernel,
                         cudaFuncAttributeMaxDynamicSharedMemorySize, FLASH_SMEM);
    flash_kernel<<<dim3(SS/64, NH, BB), 256, FLASH_SMEM>>>(p_qt, p_kt, p_qkv, p_y);

    // 4) Output projection: out[4096,2048] = y[4096,2048] * wo[2048,2048]^T
    gemm_nt<<<dim3(DD/GBN, (BB*SS)/GBM), 256>>>(p_y, wo, out,
                                                BB*SS, DD, NH*HD);
}

// round 8
// speedup vs baseline: 1.4803x; 1.4803x over previous
#include <cuda_runtime.h>
#include <cuda_bf16.h>
#include <math.h>
#include <stdint.h>

// Problem constants
#define BB   2
#define SS   2048
#define DD   2048
#define NH   16
#define NKV  4
#define HD   128
#define EHEADS (NH + 2*NKV)          // 24
#define QKVE (EHEADS * HD)           // 3072

// ---------------- scratch (device globals; no allocation allowed) ----------
__device__ __align__(16) float g_qkv[(size_t)BB * SS * QKVE];     // [4096][3072]
__device__ __align__(16) float g_qt [(size_t)BB * NH  * HD * SS]; // [B][NH][HD][S]
__device__ __align__(16) float g_kt [(size_t)BB * NKV * HD * SS]; // [B][NKV][HD][S]
__device__ __align__(16) float g_y  [(size_t)BB * SS * DD];       // [4096][2048]
// bf16 split operands (hi + residual lo)
__device__ __align__(16) __nv_bfloat16 g_xh [(size_t)BB*SS*DD];
__device__ __align__(16) __nv_bfloat16 g_xl [(size_t)BB*SS*DD];
__device__ __align__(16) __nv_bfloat16 g_wqh[(size_t)QKVE*DD];
__device__ __align__(16) __nv_bfloat16 g_wql[(size_t)QKVE*DD];
__device__ __align__(16) __nv_bfloat16 g_woh[(size_t)DD*DD];
__device__ __align__(16) __nv_bfloat16 g_wol[(size_t)DD*DD];
__device__ __align__(16) __nv_bfloat16 g_yh [(size_t)BB*SS*DD];
__device__ __align__(16) __nv_bfloat16 g_yl [(size_t)BB*SS*DD];

// ---------------- helpers ----------------------------------------------------
__device__ __forceinline__ unsigned long long pack2(float x) {
    unsigned long long r;
    asm("mov.b64 %0, {%1, %1};" : "=l"(r) : "f"(x));
    return r;
}
__device__ __forceinline__ void fma2(unsigned long long& c,
                                     unsigned long long a,
                                     unsigned long long b) {
    asm("fma.rn.f32x2 %0, %1, %2, %0;" : "+l"(c) : "l"(a), "l"(b));
}
__device__ __forceinline__ void mul2(unsigned long long& c, unsigned long long a) {
    asm("mul.rn.f32x2 %0, %0, %1;" : "+l"(c) : "l"(a));
}
__device__ __forceinline__ float2 unpack2(unsigned long long v) {
    float2 r;
    asm("mov.b64 {%0, %1}, %2;" : "=f"(r.x), "=f"(r.y) : "l"(v));
    return r;
}
__device__ __forceinline__ float ex2f(float x) {
    float y;
    asm("ex2.approx.ftz.f32 %0, %1;" : "=f"(y) : "f"(x));
    return y;
}
__device__ __forceinline__ uint32_t s2u(const void* p) {
    uint32_t r;
    asm("{ .reg .u64 t; cvta.to.shared.u64 t, %1; cvt.u32.u64 %0, t; }" : "=r"(r) : "l"(p));
    return r;
}
__device__ __forceinline__ void cp16(uint32_t dst, const void* src) {
    asm volatile("cp.async.cg.shared.global [%0], [%1], 16;" :: "r"(dst), "l"(src));
}

#define LDSM4(r, addr) \
    asm volatile("ldmatrix.sync.aligned.m8n8.x4.shared.b16 {%0,%1,%2,%3}, [%4];" \
        : "=r"((r)[0]), "=r"((r)[1]), "=r"((r)[2]), "=r"((r)[3]) : "r"(addr))

#define MMA_BF16(d, a, b0v, b1v) \
    asm volatile("mma.sync.aligned.m16n8k16.row.col.f32.bf16.bf16.f32 " \
        "{%0,%1,%2,%3}, {%4,%5,%6,%7}, {%8,%9}, {%0,%1,%2,%3};" \
        : "+f"((d)[0]), "+f"((d)[1]), "+f"((d)[2]), "+f"((d)[3]) \
        : "r"((a)[0]), "r"((a)[1]), "r"((a)[2]), "r"((a)[3]), "r"(b0v), "r"(b1v))

// ---------------- split fp32 -> bf16 hi/lo ----------------------------------
__global__ void __launch_bounds__(256) split_bf16(const float4* __restrict__ src,
                                                  uint2* __restrict__ hi,
                                                  uint2* __restrict__ lo,
                                                  int n4)
{
    int i = blockIdx.x * 256 + threadIdx.x;
    if (i >= n4) return;
    float4 v = src[i];
    float2 a = make_float2(v.x, v.y);
    float2 b = make_float2(v.z, v.w);
    __nv_bfloat162 ha = __float22bfloat162_rn(a);
    __nv_bfloat162 hb = __float22bfloat162_rn(b);
    float2 ra = make_float2(a.x - __low2float(ha), a.y - __high2float(ha));
    float2 rb = make_float2(b.x - __low2float(hb), b.y - __high2float(hb));
    __nv_bfloat162 la = __float22bfloat162_rn(ra);
    __nv_bfloat162 lb = __float22bfloat162_rn(rb);
    hi[i] = make_uint2(*reinterpret_cast<unsigned int*>(&ha),
                       *reinterpret_cast<unsigned int*>(&hb));
    lo[i] = make_uint2(*reinterpret_cast<unsigned int*>(&la),
                       *reinterpret_cast<unsigned int*>(&lb));
}

// ---------------- mma.sync GEMM: C[M,N] = A[M,K]*B[N,K]^T (bf16x3, f32 acc) --
// CTA tile 128x128, K-chunk 32. 8 warps: warp (wr,wc) owns 64x32.
// smem per stage: 4 arrays (Ah,Al,Bh,Bl) of 128 rows x 32 bf16, row stride 40
// bf16 (80 B) -> ldmatrix octets hit all 32 banks exactly once (conflict-free).
#define STG   10240                 // bytes per array per stage (128*80)
#define STAGE (4*STG)               // 40960
#define GSMEM (2*STAGE)             // 81920

__global__ void __launch_bounds__(256) gemm_mma(
    const __nv_bfloat16* __restrict__ Ah, const __nv_bfloat16* __restrict__ Al,
    const __nv_bfloat16* __restrict__ Bh, const __nv_bfloat16* __restrict__ Bl,
    float* __restrict__ C, int N, int K)
{
    extern __shared__ __align__(16) char smg[];
    const uint32_t sb = s2u(smg);
    const int tid  = threadIdx.x;
    const int lane = tid & 31;
    const int wid  = tid >> 5;
    const int wr   = wid >> 2;      // 0..1 (64-row slab)
    const int wc   = wid & 3;       // 0..3 (32-col slab)
    const int bm   = blockIdx.y << 7;
    const int bn   = blockIdx.x << 7;
    const int nk   = K >> 5;

    float acc[4][4][4];
    #pragma unroll
    for (int i = 0; i < 4; i++)
        #pragma unroll
        for (int j = 0; j < 4; j++)
            #pragma unroll
            for (int r = 0; r < 4; r++) acc[i][j][r] = 0.f;

    // ldmatrix per-lane octet addressing
    const int l8     = lane & 7;
    const int rowA   = ((lane >> 3) & 1) * 8 + l8;   // A: oct0/2 rows 0-7, oct1/3 rows 8-15
    const int kbyteA = ((lane >> 4) & 1) * 16;       // A: oct2/3 -> k+8
    const int rowB   = ((lane >> 4) & 1) * 8 + l8;   // B: oct0/1 n-rows 0-7, oct2/3 rows 8-15
    const int byteB  = ((lane >> 3) & 1) * 16;       // B: oct1/3 -> k+8

    // stage fill: 512 cp16 per array, 2 per thread per array
    auto fill = [&](int s, int kc) {
        const int k0 = kc << 5;
        const uint32_t dst = sb + s * STAGE;
        #pragma unroll
        for (int i = 0; i < 2; i++) {
            int lin = tid + i * 256;
            int row = lin >> 2;
            int ch  = lin & 3;
            uint32_t so = row * 80 + ch * 16;
            size_t ga = (size_t)(bm + row) * K + k0 + ch * 8;
            size_t gb = (size_t)(bn + row) * K + k0 + ch * 8;
            cp16(dst +           so, Ah + ga);
            cp16(dst + STG     + so, Al + ga);
            cp16(dst + 2*STG   + so, Bh + gb);
            cp16(dst + 3*STG   + so, Bl + gb);
        }
    };

    fill(0, 0);
    asm volatile("cp.async.commit_group;" ::: "memory");

    for (int t = 0; t < nk; ++t) {
        if (t + 1 < nk) {
            fill((t + 1) & 1, t + 1);
            asm volatile("cp.async.commit_group;" ::: "memory");
            asm volatile("cp.async.wait_group 1;" ::: "memory");
        } else {
            asm volatile("cp.async.wait_group 0;" ::: "memory");
        }
        __syncthreads();

        const uint32_t st = sb + (t & 1) * STAGE;
        #pragma unroll
        for (int kh = 0; kh < 2; kh++) {
            uint32_t ah[4][4], al[4][4];
            #pragma unroll
            for (int mi = 0; mi < 4; mi++) {
                uint32_t aaddr = st + (uint32_t)(wr*64 + mi*16 + rowA) * 80
                               + kh*32 + kbyteA;
                LDSM4(ah[mi], aaddr);
                LDSM4(al[mi], aaddr + STG);
            }
            #pragma unroll
            for (int np = 0; np < 2; np++) {
                uint32_t baddr = st + 2*STG + (uint32_t)(wc*32 + np*16 + rowB) * 80
                               + kh*32 + byteB;
                uint32_t bh[4], bl[4];
                LDSM4(bh, baddr);
                LDSM4(bl, baddr + STG);
                #pragma unroll
                for (int mi = 0; mi < 4; mi++) {
                    MMA_BF16(acc[mi][2*np],   ah[mi], bh[0], bh[1]);
                    MMA_BF16(acc[mi][2*np],   ah[mi], bl[0], bl[1]);
                    MMA_BF16(acc[mi][2*np],   al[mi], bh[0], bh[1]);
                    MMA_BF16(acc[mi][2*np+1], ah[mi], bh[2], bh[3]);
                    MMA_BF16(acc[mi][2*np+1], ah[mi], bl[2], bl[3]);
                    MMA_BF16(acc[mi][2*np+1], al[mi], bh[2], bh[3]);
                }
            }
        }
        __syncthreads();
    }

    // epilogue: d0,d1 = (row lane/4, col 2(lane%4)+{0,1}); d2,d3 = row+8
    const int er = lane >> 2;
    const int ec = (lane & 3) * 2;
    #pragma unroll
    for (int mi = 0; mi < 4; mi++) {
        #pragma unroll
        for (int nn = 0; nn < 4; nn++) {
            float* cp0 = C + (size_t)(bm + wr*64 + mi*16 + er) * N
                           + bn + wc*32 + nn*8 + ec;
            *(float2*)cp0         = make_float2(acc[mi][nn][0], acc[mi][nn][1]);
            *(float2*)(cp0 + 8*N) = make_float2(acc[mi][nn][2], acc[mi][nn][3]);
        }
    }
}

// ---------------- RMSNorm + RoPE + transpose to [B,H][HD][S] ----------------
#define QSCALE 0.12751943f   // (1/sqrt(128)) * log2(e)
__global__ void __launch_bounds__(256) norm_rope_t(const float* __restrict__ qkv,
                                                   const float* __restrict__ freqs,
                                                   const float* __restrict__ qw,
                                                   const float* __restrict__ kw,
                                                   float* __restrict__ qt,
                                                   float* __restrict__ kt)
{
    __shared__ float st[128 * 33];
    const int s0   = blockIdx.x * 32;
    const int h    = blockIdx.y;
    const int b    = blockIdx.z;
    const int w    = threadIdx.x >> 5;
    const int lane = threadIdx.x & 31;
    const bool isq = (h < NH);
    const float fold = isq ? QSCALE : 1.0f;
    const float* wn  = isq ? qw : kw;
    const float4 wv  = *(const float4*)(wn + lane*4);

    #pragma unroll
    for (int ii = 0; ii < 4; ii++) {
        const int sl = w*4 + ii;
        const int s  = s0 + sl;
        const float* src = qkv + ((size_t)(b*SS + s)) * QKVE + h * HD;
        float4 v = *(const float4*)(src + lane*4);
        float ssum = v.x*v.x + v.y*v.y + v.z*v.z + v.w*v.w;
        #pragma unroll
        for (int off = 16; off >= 1; off >>= 1)
            ssum += __shfl_xor_sync(0xffffffffu, ssum, off);
        float inv = rsqrtf(ssum * (1.0f / HD) + 1e-6f) * fold;
        float x0 = v.x * inv * wv.x;
        float x1 = v.y * inv * wv.y;
        float x2 = v.z * inv * wv.z;
        float x3 = v.w * inv * wv.w;
        float4 f = *(const float4*)(freqs + (size_t)s*128 + lane*4);
        st[(lane*4+0)*33 + sl] = x0*f.x - x1*f.y;
        st[(lane*4+1)*33 + sl] = x1*f.x + x0*f.y;
        st[(lane*4+2)*33 + sl] = x2*f.z - x3*f.w;
        st[(lane*4+3)*33 + sl] = x3*f.z + x2*f.w;
    }
    __syncthreads();

    float* dst = isq ? (qt + ((size_t)(b*NH  + h))      * HD * SS)
                     : (kt + ((size_t)(b*NKV + h - NH)) * HD * SS);
    #pragma unroll
    for (int it = 0; it < 4; it++) {
        int lin = threadIdx.x + it*256;
        int d   = lin >> 3;
        int sl4 = (lin & 7) << 2;
        float4 o = make_float4(st[d*33 + sl4 + 0], st[d*33 + sl4 + 1],
                               st[d*33 + sl4 + 2], st[d*33 + sl4 + 3]);
        *(float4*)(dst + (size_t)d*SS + s0 + sl4) = o;
    }
}

// ---------------- Flash attention (causal, GQA), BM=64 ----------------------
#define QKS 64
#define FVS 128
#define PRS 68
#define FLASH_SMEM ((128*QKS + 128*QKS + 64*FVS) * 4)   // 98304 B

__global__ void __launch_bounds__(256, 2) flash_kernel(const float* __restrict__ Qt,
                                                       const float* __restrict__ Kt,
                                                       const float* __restrict__ qkv,
                                                       float* __restrict__ Y)
{
    extern __shared__ __align__(16) float sm[];
    float* Qs = sm;                    // [d][r]  128 x 64 (pre-scaled)
    float* Ks = Qs + 128*QKS;          // [d][c]  128 x 64
    float* Vs = Ks + 128*QKS;          // [kk][d]  64 x 128
    float* Ps = Ks;                    // [c][r]   64 x 68  (aliases Ks)

    const int tid = threadIdx.x;
    const int qb  = gridDim.x - 1 - blockIdx.x;
    const int h   = blockIdx.y;
    const int b   = blockIdx.z;
    const int q0  = qb * 64;

    const float* qsrc = Qt  + ((size_t)(b*NH  + h)        * HD) * SS + q0;
    const float* ksrc = Kt  + ((size_t)(b*NKV + (h >> 2)) * HD) * SS;
    const float* vsrc = qkv + ((size_t)b*SS) * QKVE + (NH + NKV + (h >> 2)) * HD;

    #pragma unroll
    for (int it = 0; it < 8; it++) {
        int lin = tid + it*256;
        int d   = lin >> 4;
        int rr  = (lin & 15) << 2;
        *(float4*)&Qs[d*QKS + rr] = *(const float4*)(qsrc + (size_t)d*SS + rr);
    }

    const int ty = tid >> 4, tx = tid & 15;
    unsigned long long o2[4][4];
    float m[4], l[4];
    #pragma unroll
    for (int i = 0; i < 4; i++) {
        m[i] = -1e30f; l[i] = 0.f;
        #pragma unroll
        for (int j = 0; j < 4; j++) o2[i][j] = 0ull;
    }
    __syncthreads();

    const int nkb = qb + 1;
    for (int kb = 0; kb < nkb; ++kb) {
        const int k0 = kb * 64;
        #pragma unroll
        for (int it = 0; it < 8; it++) {
            int lin = tid + it*256;
            int d   = lin >> 4;
            int c4  = (lin & 15) << 2;
            *(float4*)&Ks[d*QKS + c4] = *(const float4*)(ksrc + (size_t)d*SS + k0 + c4);
            int r   = lin >> 5;
            int d4  = (lin & 31) << 2;
            *(float4*)&Vs[r*FVS + d4] = *(const float4*)(vsrc + (size_t)(k0 + r)*QKVE + d4);
        }
        __syncthreads();

        unsigned long long acc0[4], acc1[4];
        #pragma unroll
        for (int j = 0; j < 4; j++) { acc0[j] = 0ull; acc1[j] = 0ull; }

        #pragma unroll 2
        for (int d = 0; d < 128; ++d) {
            ulonglong2 qp = *(const ulonglong2*)&Qs[d*QKS + ty*4];
            float4 kk4 = *(const float4*)&Ks[d*QKS + tx*4];
            unsigned long long b0 = pack2(kk4.x), b1 = pack2(kk4.y);
            unsigned long long b2 = pack2(kk4.z), b3 = pack2(kk4.w);
            fma2(acc0[0], qp.x, b0); fma2(acc1[0], qp.y, b0);
            fma2(acc0[1], qp.x, b1); fma2(acc1[1], qp.y, b1);
            fma2(acc0[2], qp.x, b2); fma2(acc1[2], qp.y, b2);
            fma2(acc0[3], qp.x, b3); fma2(acc1[3], qp.y, b3);
        }
        __syncthreads();

        float s[4][4];
        #pragma unroll
        for (int j = 0; j < 4; j++) {
            float2 p01 = unpack2(acc0[j]);
            float2 p23 = unpack2(acc1[j]);
            s[0][j] = p01.x; s[1][j] = p01.y;
            s[2][j] = p23.x; s[3][j] = p23.y;
        }

        if (kb == qb) {
            #pragma unroll
            for (int i = 0; i < 4; i++)
                #pragma unroll
                for (int j = 0; j < 4; j++)
                    if (k0 + tx*4 + j > q0 + ty*4 + i) s[i][j] = -1e30f;
        }

        #pragma unroll
        for (int i = 0; i < 4; i++) {
            float mx = fmaxf(fmaxf(s[i][0], s[i][1]), fmaxf(s[i][2], s[i][3]));
            #pragma unroll
            for (int off = 8; off >= 1; off >>= 1)
                mx = fmaxf(mx, __shfl_xor_sync(0xffffffffu, mx, off, 16));
            float mn   = fmaxf(m[i], mx);
            float corr = ex2f(m[i] - mn);
            m[i] = mn;
            float rs = 0.f;
            #pragma unroll
            for (int j = 0; j < 4; j++) {
                float p = ex2f(s[i][j] - mn);
                s[i][j] = p;
                rs += p;
            }
            #pragma unroll
            for (int off = 8; off >= 1; off >>= 1)
                rs += __shfl_xor_sync(0xffffffffu, rs, off, 16);
            l[i] = l[i] * corr + rs;
            unsigned long long c2 = pack2(corr);
            #pragma unroll
            for (int j = 0; j < 4; j++) mul2(o2[i][j], c2);
        }

        #pragma unroll
        for (int j = 0; j < 4; j++) {
            *(float4*)&Ps[(tx*4 + j)*PRS + ty*4]
                = make_float4(s[0][j], s[1][j], s[2][j], s[3][j]);
        }
        __syncthreads();

        #pragma unroll 2
        for (int kk = 0; kk < 64; ++kk) {
            float4 pv = *(const float4*)&Ps[kk*PRS + ty*4];
            unsigned long long p0 = pack2(pv.x), p1 = pack2(pv.y);
            unsigned long long p2 = pack2(pv.z), p3 = pack2(pv.w);
            ulonglong2 va = *(const ulonglong2*)&Vs[kk*FVS + tx*4];
            ulonglong2 vb = *(const ulonglong2*)&Vs[kk*FVS + 64 + tx*4];
            fma2(o2[0][0], p0, va.x); fma2(o2[0][1], p0, va.y);
            fma2(o2[0][2], p0, vb.x); fma2(o2[0][3], p0, vb.y);
            fma2(o2[1][0], p1, va.x); fma2(o2[1][1], p1, va.y);
            fma2(o2[1][2], p1, vb.x); fma2(o2[1][3], p1, vb.y);
            fma2(o2[2][0], p2, va.x); fma2(o2[2][1], p2, va.y);
            fma2(o2[2][2], p2, vb.x); fma2(o2[2][3], p2, vb.y);
            fma2(o2[3][0], p3, va.x); fma2(o2[3][1], p3, va.y);
            fma2(o2[3][2], p3, vb.x); fma2(o2[3][3], p3, vb.y);
        }
        __syncthreads();
    }

    #pragma unroll
    for (int i = 0; i < 4; i++) {
        float inv = 1.0f / l[i];
        int row = q0 + ty*4 + i;
        float* yp = Y + ((size_t)(b*SS + row)) * DD + h*HD;
        float2 c0 = unpack2(o2[i][0]);
        float2 c1 = unpack2(o2[i][1]);
        float2 c2 = unpack2(o2[i][2]);
        float2 c3 = unpack2(o2[i][3]);
        *(float4*)(yp + tx*4)      = make_float4(c0.x*inv, c0.y*inv, c1.x*inv, c1.y*inv);
        *(float4*)(yp + 64 + tx*4) = make_float4(c2.x*inv, c2.y*inv, c3.x*inv, c3.y*inv);
    }
}

// ---------------- launch ----------------------------------------------------
extern "C" void kernel_launch(void* const* d_in, const int* in_sizes, int n_in,
                              void* d_out, int out_size)
{
    const float* x     = (const float*)d_in[0];
    const float* freqs = (const float*)d_in[1];
    const float* wqkv  = (const float*)d_in[2];
    const float* wo    = (const float*)d_in[3];
    const float* qw    = (const float*)d_in[4];
    const float* kw    = (const float*)d_in[5];
    float* out = (float*)d_out;

    float *p_qkv, *p_qt, *p_kt, *p_y;
    __nv_bfloat16 *p_xh, *p_xl, *p_wqh, *p_wql, *p_woh, *p_wol, *p_yh, *p_yl;
    cudaGetSymbolAddress((void**)&p_qkv, g_qkv);
    cudaGetSymbolAddress((void**)&p_qt,  g_qt);
    cudaGetSymbolAddress((void**)&p_kt,  g_kt);
    cudaGetSymbolAddress((void**)&p_y,   g_y);
    cudaGetSymbolAddress((void**)&p_xh,  g_xh);
    cudaGetSymbolAddress((void**)&p_xl,  g_xl);
    cudaGetSymbolAddress((void**)&p_wqh, g_wqh);
    cudaGetSymbolAddress((void**)&p_wql, g_wql);
    cudaGetSymbolAddress((void**)&p_woh, g_woh);
    cudaGetSymbolAddress((void**)&p_wol, g_wol);
    cudaGetSymbolAddress((void**)&p_yh,  g_yh);
    cudaGetSymbolAddress((void**)&p_yl,  g_yl);

    cudaFuncSetAttribute(gemm_mma,
                         cudaFuncAttributeMaxDynamicSharedMemorySize, GSMEM);
    cudaFuncSetAttribute(flash_kernel,
                         cudaFuncAttributeMaxDynamicSharedMemorySize, FLASH_SMEM);

    const int n4_x  = BB*SS*DD / 4;
    const int n4_wq = QKVE*DD  / 4;
    const int n4_wo = DD*DD    / 4;

    // 0) split inputs into bf16 hi/lo
    split_bf16<<<n4_x /256, 256>>>((const float4*)x,    (uint2*)p_xh,  (uint2*)p_xl,  n4_x);
    split_bf16<<<n4_wq/256, 256>>>((const float4*)wqkv, (uint2*)p_wqh, (uint2*)p_wql, n4_wq);
    split_bf16<<<n4_wo/256, 256>>>((const float4*)wo,   (uint2*)p_woh, (uint2*)p_wol, n4_wo);

    // 1) QKV projection on tensor cores (mma.sync): [4096,3072] = x * wqkv^T
    gemm_mma<<<dim3(QKVE/128, (BB*SS)/128), 256, GSMEM>>>(
        p_xh, p_xl, p_wqh, p_wql, p_qkv, QKVE, DD);

    // 2) RMSNorm + RoPE + transpose (Q pre-scaled); V stays in g_qkv
    norm_rope_t<<<dim3(SS/32, NH + NKV, BB), 256>>>(p_qkv, freqs, qw, kw,
                                                    p_qt, p_kt);

    // 3) Flash attention (causal, GQA)
    flash_kernel<<<dim3(SS/64, NH, BB), 256, FLASH_SMEM>>>(p_qt, p_kt, p_qkv, p_y);

    // 4) split y, output projection on tensor cores
    split_bf16<<<n4_x/256, 256>>>((const float4*)p_y, (uint2*)p_yh, (uint2*)p_yl, n4_x);
    gemm_mma<<<dim3(DD/128, (BB*SS)/128), 256, GSMEM>>>(
        p_yh, p_yl, p_woh, p_wol, out, DD, NH*HD);
}

// round 9
// speedup vs baseline: 2.2760x; 1.5375x over previous
#include <cuda_runtime.h>
#include <cuda_bf16.h>
#include <math.h>
#include <stdint.h>

// Problem constants
#define BB   2
#define SS   2048
#define DD   2048
#define NH   16
#define NKV  4
#define HD   128
#define EHEADS (NH + 2*NKV)          // 24
#define QKVE (EHEADS * HD)           // 3072

// ---------------- scratch (device globals; no allocation allowed) ----------
__device__ __align__(16) float g_qkv[(size_t)BB * SS * QKVE];
__device__ __align__(16) float g_y  [(size_t)BB * SS * DD];
// bf16 split operands for projections
__device__ __align__(16) __nv_bfloat16 g_xh [(size_t)BB*SS*DD];
__device__ __align__(16) __nv_bfloat16 g_xl [(size_t)BB*SS*DD];
__device__ __align__(16) __nv_bfloat16 g_wqh[(size_t)QKVE*DD];
__device__ __align__(16) __nv_bfloat16 g_wql[(size_t)QKVE*DD];
__device__ __align__(16) __nv_bfloat16 g_woh[(size_t)DD*DD];
__device__ __align__(16) __nv_bfloat16 g_wol[(size_t)DD*DD];
__device__ __align__(16) __nv_bfloat16 g_yh [(size_t)BB*SS*DD];
__device__ __align__(16) __nv_bfloat16 g_yl [(size_t)BB*SS*DD];
// bf16 split Q/K/V for flash ([B,H,S,HD] row-major)
__device__ __align__(16) __nv_bfloat16 g_qh [(size_t)BB*NH *SS*HD];
__device__ __align__(16) __nv_bfloat16 g_ql [(size_t)BB*NH *SS*HD];
__device__ __align__(16) __nv_bfloat16 g_kh [(size_t)BB*NKV*SS*HD];
__device__ __align__(16) __nv_bfloat16 g_kl [(size_t)BB*NKV*SS*HD];
__device__ __align__(16) __nv_bfloat16 g_vh [(size_t)BB*NKV*SS*HD];
__device__ __align__(16) __nv_bfloat16 g_vl [(size_t)BB*NKV*SS*HD];

// ---------------- helpers ----------------------------------------------------
__device__ __forceinline__ float ex2f(float x) {
    float y;
    asm("ex2.approx.ftz.f32 %0, %1;" : "=f"(y) : "f"(x));
    return y;
}
__device__ __forceinline__ uint32_t s2u(const void* p) {
    uint32_t r;
    asm("{ .reg .u64 t; cvta.to.shared.u64 t, %1; cvt.u32.u64 %0, t; }" : "=r"(r) : "l"(p));
    return r;
}
__device__ __forceinline__ void cp16(uint32_t dst, const void* src) {
    asm volatile("cp.async.cg.shared.global [%0], [%1], 16;" :: "r"(dst), "l"(src));
}
__device__ __forceinline__ uint32_t cvt2(float hi, float lo) {
    uint32_t r;
    asm("cvt.rn.bf16x2.f32 %0, %1, %2;" : "=r"(r) : "f"(hi), "f"(lo));
    return r;
}
__device__ __forceinline__ float lo_f(uint32_t u) { return __uint_as_float(u << 16); }
__device__ __forceinline__ float hi_f(uint32_t u) { return __uint_as_float(u & 0xffff0000u); }

#define LDSM4(r, addr) \
    asm volatile("ldmatrix.sync.aligned.m8n8.x4.shared.b16 {%0,%1,%2,%3}, [%4];" \
        : "=r"((r)[0]), "=r"((r)[1]), "=r"((r)[2]), "=r"((r)[3]) : "r"(addr))
#define LDSM4T(r, addr) \
    asm volatile("ldmatrix.sync.aligned.m8n8.x4.trans.shared.b16 {%0,%1,%2,%3}, [%4];" \
        : "=r"((r)[0]), "=r"((r)[1]), "=r"((r)[2]), "=r"((r)[3]) : "r"(addr))

#define MMA_BF16(d, a, b0v, b1v) \
    asm volatile("mma.sync.aligned.m16n8k16.row.col.f32.bf16.bf16.f32 " \
        "{%0,%1,%2,%3}, {%4,%5,%6,%7}, {%8,%9}, {%0,%1,%2,%3};" \
        : "+f"((d)[0]), "+f"((d)[1]), "+f"((d)[2]), "+f"((d)[3]) \
        : "r"((a)[0]), "r"((a)[1]), "r"((a)[2]), "r"((a)[3]), "r"(b0v), "r"(b1v))

// ---------------- split fp32 -> bf16 hi/lo ----------------------------------
__global__ void __launch_bounds__(256) split_bf16(const float4* __restrict__ src,
                                                  uint2* __restrict__ hi,
                                                  uint2* __restrict__ lo,
                                                  int n4)
{
    int i = blockIdx.x * 256 + threadIdx.x;
    if (i >= n4) return;
    float4 v = src[i];
    uint32_t h01 = cvt2(v.y, v.x);
    uint32_t h23 = cvt2(v.w, v.z);
    uint32_t l01 = cvt2(v.y - hi_f(h01), v.x - lo_f(h01));
    uint32_t l23 = cvt2(v.w - hi_f(h23), v.z - lo_f(h23));
    hi[i] = make_uint2(h01, h23);
    lo[i] = make_uint2(l01, l23);
}

// ---------------- mma.sync GEMM: C[M,N] = A[M,K]*B[N,K]^T (bf16x3, f32 acc) --
#define STG   10240
#define STAGE (4*STG)
#define GSMEM (2*STAGE)

__global__ void __launch_bounds__(256) gemm_mma(
    const __nv_bfloat16* __restrict__ Ah, const __nv_bfloat16* __restrict__ Al,
    const __nv_bfloat16* __restrict__ Bh, const __nv_bfloat16* __restrict__ Bl,
    float* __restrict__ C, int N, int K)
{
    extern __shared__ __align__(16) char smg[];
    const uint32_t sb = s2u(smg);
    const int tid  = threadIdx.x;
    const int lane = tid & 31;
    const int wid  = tid >> 5;
    const int wr   = wid >> 2;
    const int wc   = wid & 3;
    const int bm   = blockIdx.y << 7;
    const int bn   = blockIdx.x << 7;
    const int nk   = K >> 5;

    float acc[4][4][4];
    #pragma unroll
    for (int i = 0; i < 4; i++)
        #pragma unroll
        for (int j = 0; j < 4; j++)
            #pragma unroll
            for (int r = 0; r < 4; r++) acc[i][j][r] = 0.f;

    const int l8     = lane & 7;
    const int rowA   = ((lane >> 3) & 1) * 8 + l8;
    const int kbyteA = ((lane >> 4) & 1) * 16;
    const int rowB   = ((lane >> 4) & 1) * 8 + l8;
    const int byteB  = ((lane >> 3) & 1) * 16;

    auto fill = [&](int s, int kc) {
        const int k0 = kc << 5;
        const uint32_t dst = sb + s * STAGE;
        #pragma unroll
        for (int i = 0; i < 2; i++) {
            int lin = tid + i * 256;
            int row = lin >> 2;
            int ch  = lin & 3;
            uint32_t so = row * 80 + ch * 16;
            size_t ga = (size_t)(bm + row) * K + k0 + ch * 8;
            size_t gb = (size_t)(bn + row) * K + k0 + ch * 8;
            cp16(dst +           so, Ah + ga);
            cp16(dst + STG     + so, Al + ga);
            cp16(dst + 2*STG   + so, Bh + gb);
            cp16(dst + 3*STG   + so, Bl + gb);
        }
    };

    fill(0, 0);
    asm volatile("cp.async.commit_group;" ::: "memory");

    for (int t = 0; t < nk; ++t) {
        if (t + 1 < nk) {
            fill((t + 1) & 1, t + 1);
            asm volatile("cp.async.commit_group;" ::: "memory");
            asm volatile("cp.async.wait_group 1;" ::: "memory");
        } else {
            asm volatile("cp.async.wait_group 0;" ::: "memory");
        }
        __syncthreads();

        const uint32_t st = sb + (t & 1) * STAGE;
        #pragma unroll
        for (int kh = 0; kh < 2; kh++) {
            uint32_t ah[4][4], al[4][4];
            #pragma unroll
            for (int mi = 0; mi < 4; mi++) {
                uint32_t aaddr = st + (uint32_t)(wr*64 + mi*16 + rowA) * 80
                               + kh*32 + kbyteA;
                LDSM4(ah[mi], aaddr);
                LDSM4(al[mi], aaddr + STG);
            }
            #pragma unroll
            for (int np = 0; np < 2; np++) {
                uint32_t baddr = st + 2*STG + (uint32_t)(wc*32 + np*16 + rowB) * 80
                               + kh*32 + byteB;
                uint32_t bh[4], bl[4];
                LDSM4(bh, baddr);
                LDSM4(bl, baddr + STG);
                #pragma unroll
                for (int mi = 0; mi < 4; mi++) {
                    MMA_BF16(acc[mi][2*np],   ah[mi], bh[0], bh[1]);
                    MMA_BF16(acc[mi][2*np],   ah[mi], bl[0], bl[1]);
                    MMA_BF16(acc[mi][2*np],   al[mi], bh[0], bh[1]);
                    MMA_BF16(acc[mi][2*np+1], ah[mi], bh[2], bh[3]);
                    MMA_BF16(acc[mi][2*np+1], ah[mi], bl[2], bl[3]);
                    MMA_BF16(acc[mi][2*np+1], al[mi], bh[2], bh[3]);
                }
            }
        }
        __syncthreads();
    }

    const int er = lane >> 2;
    const int ec = (lane & 3) * 2;
    #pragma unroll
    for (int mi = 0; mi < 4; mi++) {
        #pragma unroll
        for (int nn = 0; nn < 4; nn++) {
            float* cp0 = C + (size_t)(bm + wr*64 + mi*16 + er) * N
                           + bn + wc*32 + nn*8 + ec;
            *(float2*)cp0         = make_float2(acc[mi][nn][0], acc[mi][nn][1]);
            *(float2*)(cp0 + 8*N) = make_float2(acc[mi][nn][2], acc[mi][nn][3]);
        }
    }
}

// ---------------- RMSNorm + RoPE + bf16 hi/lo split --------------------------
#define QSCALE 0.12751943f   // (1/sqrt(128)) * log2(e)
__global__ void __launch_bounds__(256) norm_split(const float* __restrict__ qkv,
                                                  const float* __restrict__ freqs,
                                                  const float* __restrict__ qw,
                                                  const float* __restrict__ kw,
                                                  __nv_bfloat16* __restrict__ qh,
                                                  __nv_bfloat16* __restrict__ ql,
                                                  __nv_bfloat16* __restrict__ kh,
                                                  __nv_bfloat16* __restrict__ kl,
                                                  __nv_bfloat16* __restrict__ vh,
                                                  __nv_bfloat16* __restrict__ vl)
{
    const int wid  = threadIdx.x >> 5;
    const int lane = threadIdx.x & 31;
    const int s    = blockIdx.x * 8 + wid;
    const int h    = blockIdx.y;
    const int b    = blockIdx.z;

    const float* src = qkv + ((size_t)(b*SS + s)) * QKVE + h * HD;
    float4 v = *(const float4*)(src + lane*4);
    float x0 = v.x, x1 = v.y, x2 = v.z, x3 = v.w;

    if (h < NH + NKV) {
        float ssum = x0*x0 + x1*x1 + x2*x2 + x3*x3;
        #pragma unroll
        for (int off = 16; off >= 1; off >>= 1)
            ssum += __shfl_xor_sync(0xffffffffu, ssum, off);
        const bool isq = (h < NH);
        float inv = rsqrtf(ssum * (1.0f / HD) + 1e-6f) * (isq ? QSCALE : 1.0f);
        const float* wn = isq ? qw : kw;
        float4 wv = *(const float4*)(wn + lane*4);
        float t0 = x0 * inv * wv.x;
        float t1 = x1 * inv * wv.y;
        float t2 = x2 * inv * wv.z;
        float t3 = x3 * inv * wv.w;
        float4 f = *(const float4*)(freqs + (size_t)s*128 + lane*4);
        x0 = t0*f.x - t1*f.y;
        x1 = t1*f.x + t0*f.y;
        x2 = t2*f.z - t3*f.w;
        x3 = t3*f.z + t2*f.w;
    }

    uint32_t h01 = cvt2(x1, x0);
    uint32_t h23 = cvt2(x3, x2);
    uint32_t l01 = cvt2(x1 - hi_f(h01), x0 - lo_f(h01));
    uint32_t l23 = cvt2(x3 - hi_f(h23), x2 - lo_f(h23));

    __nv_bfloat16 *dh, *dl;
    size_t row;
    if (h < NH)            { row = (size_t)(b*NH  + h)           * SS + s; dh = qh; dl = ql; }
    else if (h < NH + NKV) { row = (size_t)(b*NKV + h - NH)      * SS + s; dh = kh; dl = kl; }
    else                   { row = (size_t)(b*NKV + h - NH - NKV)* SS + s; dh = vh; dl = vl; }
    *(uint2*)(dh + row*HD + lane*4) = make_uint2(h01, h23);
    *(uint2*)(dl + row*HD + lane*4) = make_uint2(l01, l23);
}

// ---------------- Flash attention on tensor cores (causal, GQA) --------------
// BM=128 (8 warps x 16 rows), BN=64. Q hi/lo resident in smem; K/V per tile.
#define FST 272                         // smem row stride bytes (136 bf16)
#define QH_OFF 0
#define QL_OFF (128*FST)                // 34816
#define KH_OFF (2*128*FST)              // 69632
#define KL_OFF (KH_OFF + 64*FST)        // 87040
#define VH_OFF (KL_OFF + 64*FST)        // 104448
#define VL_OFF (VH_OFF + 64*FST)        // 121856
#define FLASH_SMEM (VL_OFF + 64*FST)    // 139264

__global__ void __launch_bounds__(256) flash_mma(
    const __nv_bfloat16* __restrict__ qh, const __nv_bfloat16* __restrict__ ql,
    const __nv_bfloat16* __restrict__ kh, const __nv_bfloat16* __restrict__ kl,
    const __nv_bfloat16* __restrict__ vh, const __nv_bfloat16* __restrict__ vl,
    float* __restrict__ Y)
{
    extern __shared__ __align__(16) char smf[];
    const uint32_t sb = s2u(smf);
    const int tid  = threadIdx.x;
    const int lane = tid & 31;
    const int wid  = tid >> 5;
    const int qb   = gridDim.x - 1 - blockIdx.x;   // long blocks first
    const int h    = blockIdx.y;
    const int b    = blockIdx.z;
    const int q0   = qb * 128;
    const int hkv  = h >> 2;
    const int mrow = wid * 16;

    const __nv_bfloat16* qhp = qh + ((size_t)(b*NH  + h  ) * SS + q0) * HD;
    const __nv_bfloat16* qlp = ql + ((size_t)(b*NH  + h  ) * SS + q0) * HD;
    const __nv_bfloat16* khp = kh + ((size_t)(b*NKV + hkv) * SS) * HD;
    const __nv_bfloat16* klp = kl + ((size_t)(b*NKV + hkv) * SS) * HD;
    const __nv_bfloat16* vhp = vh + ((size_t)(b*NKV + hkv) * SS) * HD;
    const __nv_bfloat16* vlp = vl + ((size_t)(b*NKV + hkv) * SS) * HD;

    // Q tile fill (resident): 128 rows x 16 chunks x {hi,lo}
    #pragma unroll
    for (int i = 0; i < 8; i++) {
        int lin = tid + i*256;
        int r   = lin >> 4;
        int ch  = lin & 15;
        cp16(sb + QH_OFF + r*FST + ch*16, qhp + (size_t)r*HD + ch*8);
        cp16(sb + QL_OFF + r*FST + ch*16, qlp + (size_t)r*HD + ch*8);
    }

    // ldmatrix lane addressing (same pattern as gemm_mma; proven)
    const int l8 = lane & 7;
    const int rA = ((lane >> 3) & 1) * 8 + l8;   // A / trans-V row
    const int cA = ((lane >> 4) & 1) * 16;
    const int rB = ((lane >> 4) & 1) * 8 + l8;   // B (K) row
    const int cB = ((lane >> 3) & 1) * 16;
    const int lr = lane >> 2;
    const int l4 = lane & 3;

    float O[16][4];
    #pragma unroll
    for (int j = 0; j < 16; j++)
        #pragma unroll
        for (int r = 0; r < 4; r++) O[j][r] = 0.f;
    float m0v = -1e30f, m1v = -1e30f, l0v = 0.f, l1v = 0.f;

    const int nkb = 2*qb + 2;
    for (int kb = 0; kb < nkb; ++kb) {
        const int k0 = kb * 64;
        if (kb) __syncthreads();   // previous tile's compute done before refill
        #pragma unroll
        for (int i = 0; i < 4; i++) {
            int lin = tid + i*256;
            int r   = lin >> 4;
            int ch  = lin & 15;
            size_t g = (size_t)(k0 + r)*HD + ch*8;
            uint32_t so = r*FST + ch*16;
            cp16(sb + KH_OFF + so, khp + g);
            cp16(sb + KL_OFF + so, klp + g);
            cp16(sb + VH_OFF + so, vhp + g);
            cp16(sb + VL_OFF + so, vlp + g);
        }
        asm volatile("cp.async.commit_group;" ::: "memory");
        asm volatile("cp.async.wait_group 0;" ::: "memory");
        __syncthreads();

        // ---- S = Q K^T (bf16x3) ----
        float S[8][4];
        #pragma unroll
        for (int j = 0; j < 8; j++)
            #pragma unroll
            for (int r = 0; r < 4; r++) S[j][r] = 0.f;

        #pragma unroll
        for (int kc = 0; kc < 8; kc++) {
            uint32_t qa_h[4], qa_l[4];
            uint32_t qaddr = sb + QH_OFF + (uint32_t)(mrow + rA)*FST + kc*32 + cA;
            LDSM4(qa_h, qaddr);
            LDSM4(qa_l, qaddr + (QL_OFF - QH_OFF));
            #pragma unroll
            for (int ng = 0; ng < 4; ng++) {
                uint32_t kaddr = sb + KH_OFF + (uint32_t)(ng*16 + rB)*FST + kc*32 + cB;
                uint32_t bh4[4], bl4[4];
                LDSM4(bh4, kaddr);
                LDSM4(bl4, kaddr + (KL_OFF - KH_OFF));
                MMA_BF16(S[2*ng],   qa_h, bh4[0], bh4[1]);
                MMA_BF16(S[2*ng],   qa_h, bl4[0], bl4[1]);
                MMA_BF16(S[2*ng],   qa_l, bh4[0], bh4[1]);
                MMA_BF16(S[2*ng+1], qa_h, bh4[2], bh4[3]);
                MMA_BF16(S[2*ng+1], qa_h, bl4[2], bl4[3]);
                MMA_BF16(S[2*ng+1], qa_l, bh4[2], bh4[3]);
            }
        }

        // ---- causal mask on the overlap tiles ----
        if (kb >= 2*qb) {
            int row0 = q0 + mrow + lr;
            int row1 = row0 + 8;
            #pragma unroll
            for (int j = 0; j < 8; j++) {
                int c0 = k0 + 8*j + 2*l4;
                if (c0     > row0) S[j][0] = -1e30f;
                if (c0 + 1 > row0) S[j][1] = -1e30f;
                if (c0     > row1) S[j][2] = -1e30f;
                if (c0 + 1 > row1) S[j][3] = -1e30f;
            }
        }

        // ---- online softmax (log2 domain; Q pre-scaled) ----
        {
            float mx = -1e30f;
            #pragma unroll
            for (int j = 0; j < 8; j++) mx = fmaxf(mx, fmaxf(S[j][0], S[j][1]));
            mx = fmaxf(mx, __shfl_xor_sync(0xffffffffu, mx, 1));
            mx = fmaxf(mx, __shfl_xor_sync(0xffffffffu, mx, 2));
            float mn = fmaxf(m0v, mx);
            float corr = ex2f(m0v - mn);
            m0v = mn;
            float rs = 0.f;
            #pragma unroll
            for (int j = 0; j < 8; j++) {
                S[j][0] = ex2f(S[j][0] - mn);
                S[j][1] = ex2f(S[j][1] - mn);
                rs += S[j][0] + S[j][1];
            }
            rs += __shfl_xor_sync(0xffffffffu, rs, 1);
            rs += __shfl_xor_sync(0xffffffffu, rs, 2);
            l0v = l0v * corr + rs;
            #pragma unroll
            for (int j = 0; j < 16; j++) { O[j][0] *= corr; O[j][1] *= corr; }
        }
        {
            float mx = -1e30f;
            #pragma unroll
            for (int j = 0; j < 8; j++) mx = fmaxf(mx, fmaxf(S[j][2], S[j][3]));
            mx = fmaxf(mx, __shfl_xor_sync(0xffffffffu, mx, 1));
            mx = fmaxf(mx, __shfl_xor_sync(0xffffffffu, mx, 2));
            float mn = fmaxf(m1v, mx);
            float corr = ex2f(m1v - mn);
            m1v = mn;
            float rs = 0.f;
            #pragma unroll
            for (int j = 0; j < 8; j++) {
                S[j][2] = ex2f(S[j][2] - mn);
                S[j][3] = ex2f(S[j][3] - mn);
                rs += S[j][2] + S[j][3];
            }
            rs += __shfl_xor_sync(0xffffffffu, rs, 1);
            rs += __shfl_xor_sync(0xffffffffu, rs, 2);
            l1v = l1v * corr + rs;
            #pragma unroll
            for (int j = 0; j < 16; j++) { O[j][2] *= corr; O[j][3] *= corr; }
        }

        // ---- O += P V (bf16x3; P converted in registers) ----
        #pragma unroll
        for (int t = 0; t < 4; t++) {
            uint32_t Ahf[4], Alf[4];
            Ahf[0] = cvt2(S[2*t][1],   S[2*t][0]);
            Ahf[1] = cvt2(S[2*t][3],   S[2*t][2]);
            Ahf[2] = cvt2(S[2*t+1][1], S[2*t+1][0]);
            Ahf[3] = cvt2(S[2*t+1][3], S[2*t+1][2]);
            Alf[0] = cvt2(S[2*t][1]   - hi_f(Ahf[0]), S[2*t][0]   - lo_f(Ahf[0]));
            Alf[1] = cvt2(S[2*t][3]   - hi_f(Ahf[1]), S[2*t][2]   - lo_f(Ahf[1]));
            Alf[2] = cvt2(S[2*t+1][1] - hi_f(Ahf[2]), S[2*t+1][0] - lo_f(Ahf[2]));
            Alf[3] = cvt2(S[2*t+1][3] - hi_f(Ahf[3]), S[2*t+1][2] - lo_f(Ahf[3]));
            #pragma unroll
            for (int dg = 0; dg < 8; dg++) {
                uint32_t vaddr = sb + VH_OFF + (uint32_t)(t*16 + rA)*FST + dg*32 + cA;
                uint32_t vhf[4], vlf[4];
                LDSM4T(vhf, vaddr);
                LDSM4T(vlf, vaddr + (VL_OFF - VH_OFF));
                MMA_BF16(O[2*dg],   Ahf, vhf[0], vhf[1]);
                MMA_BF16(O[2*dg],   Ahf, vlf[0], vlf[1]);
                MMA_BF16(O[2*dg],   Alf, vhf[0], vhf[1]);
                MMA_BF16(O[2*dg+1], Ahf, vhf[2], vhf[3]);
                MMA_BF16(O[2*dg+1], Ahf, vlf[2], vlf[3]);
                MMA_BF16(O[2*dg+1], Alf, vhf[2], vhf[3]);
            }
        }
    }

    // ---- write O ----
    float inv0 = 1.0f / l0v;
    float inv1 = 1.0f / l1v;
    int row0 = q0 + mrow + lr;
    float* y0 = Y + (size_t)(b*SS + row0) * DD + h*HD;
    float* y1 = y0 + (size_t)8 * DD;
    #pragma unroll
    for (int j = 0; j < 16; j++) {
        *(float2*)(y0 + 8*j + 2*l4) = make_float2(O[j][0]*inv0, O[j][1]*inv0);
        *(float2*)(y1 + 8*j + 2*l4) = make_float2(O[j][2]*inv1, O[j][3]*inv1);
    }
}

// ---------------- launch ----------------------------------------------------
extern "C" void kernel_launch(void* const* d_in, const int* in_sizes, int n_in,
                              void* d_out, int out_size)
{
    const float* x     = (const float*)d_in[0];
    const float* freqs = (const float*)d_in[1];
    const float* wqkv  = (const float*)d_in[2];
    const float* wo    = (const float*)d_in[3];
    const float* qw    = (const float*)d_in[4];
    const float* kw    = (const float*)d_in[5];
    float* out = (float*)d_out;

    float *p_qkv, *p_y;
    __nv_bfloat16 *p_xh, *p_xl, *p_wqh, *p_wql, *p_woh, *p_wol, *p_yh, *p_yl;
    __nv_bfloat16 *p_qh, *p_ql, *p_kh, *p_kl, *p_vh, *p_vl;
    cudaGetSymbolAddress((void**)&p_qkv, g_qkv);
    cudaGetSymbolAddress((void**)&p_y,   g_y);
    cudaGetSymbolAddress((void**)&p_xh,  g_xh);
    cudaGetSymbolAddress((void**)&p_xl,  g_xl);
    cudaGetSymbolAddress((void**)&p_wqh, g_wqh);
    cudaGetSymbolAddress((void**)&p_wql, g_wql);
    cudaGetSymbolAddress((void**)&p_woh, g_woh);
    cudaGetSymbolAddress((void**)&p_wol, g_wol);
    cudaGetSymbolAddress((void**)&p_yh,  g_yh);
    cudaGetSymbolAddress((void**)&p_yl,  g_yl);
    cudaGetSymbolAddress((void**)&p_qh,  g_qh);
    cudaGetSymbolAddress((void**)&p_ql,  g_ql);
    cudaGetSymbolAddress((void**)&p_kh,  g_kh);
    cudaGetSymbolAddress((void**)&p_kl,  g_kl);
    cudaGetSymbolAddress((void**)&p_vh,  g_vh);
    cudaGetSymbolAddress((void**)&p_vl,  g_vl);

    cudaFuncSetAttribute(gemm_mma,
                         cudaFuncAttributeMaxDynamicSharedMemorySize, GSMEM);
    cudaFuncSetAttribute(flash_mma,
                         cudaFuncAttributeMaxDynamicSharedMemorySize, FLASH_SMEM);

    const int n4_x  = BB*SS*DD / 4;
    const int n4_wq = QKVE*DD  / 4;
    const int n4_wo = DD*DD    / 4;

    // 0) split inputs
    split_bf16<<<n4_x /256, 256>>>((const float4*)x,    (uint2*)p_xh,  (uint2*)p_xl,  n4_x);
    split_bf16<<<n4_wq/256, 256>>>((const float4*)wqkv, (uint2*)p_wqh, (uint2*)p_wql, n4_wq);
    split_bf16<<<n4_wo/256, 256>>>((const float4*)wo,   (uint2*)p_woh, (uint2*)p_wol, n4_wo);

    // 1) QKV projection (tensor cores)
    gemm_mma<<<dim3(QKVE/128, (BB*SS)/128), 256, GSMEM>>>(
        p_xh, p_xl, p_wqh, p_wql, p_qkv, QKVE, DD);

    // 2) RMSNorm + RoPE + bf16 split (Q pre-scaled by scale*log2e)
    norm_split<<<dim3(SS/8, EHEADS, BB), 256>>>(p_qkv, freqs, qw, kw,
                                                p_qh, p_ql, p_kh, p_kl, p_vh, p_vl);

    // 3) Flash attention (tensor cores, causal, GQA)
    flash_mma<<<dim3(SS/128, NH, BB), 256, FLASH_SMEM>>>(
        p_qh, p_ql, p_kh, p_kl, p_vh, p_vl, p_y);

    // 4) split y, output projection (tensor cores)
    split_bf16<<<n4_x/256, 256>>>((const float4*)p_y, (uint2*)p_yh, (uint2*)p_yl, n4_x);
    gemm_mma<<<dim3(DD/128, (BB*SS)/128), 256, GSMEM>>>(
        p_yh, p_yl, p_woh, p_wol, out, DD, NH*HD);
}

// round 11
// speedup vs baseline: 2.8917x; 1.2705x over previous
#include <cuda_runtime.h>
#include <cuda_fp16.h>
#include <cuda_bf16.h>
#include <math.h>
#include <stdint.h>

// Problem constants
#define BB   2
#define SS   2048
#define DD   2048
#define NH   16
#define NKV  4
#define HD   128
#define EHEADS (NH + 2*NKV)          // 24
#define QKVE (EHEADS * HD)           // 3072

// ---------------- scratch (device globals; no allocation allowed) ----------
__device__ __align__(16) float g_qkv[(size_t)BB * SS * QKVE];
// fp16 operands (QKV projection only)
__device__ __align__(16) __half g_xh [(size_t)BB*SS*DD];
__device__ __align__(16) __half g_wqh[(size_t)QKVE*DD];
// bf16 split operands (out projection + flash)
__device__ __align__(16) __nv_bfloat16 g_woh[(size_t)DD*DD];
__device__ __align__(16) __nv_bfloat16 g_wol[(size_t)DD*DD];
__device__ __align__(16) __nv_bfloat16 g_yh [(size_t)BB*SS*DD];
__device__ __align__(16) __nv_bfloat16 g_yl [(size_t)BB*SS*DD];
__device__ __align__(16) __nv_bfloat16 g_qh [(size_t)BB*NH *SS*HD];
__device__ __align__(16) __nv_bfloat16 g_ql [(size_t)BB*NH *SS*HD];
__device__ __align__(16) __nv_bfloat16 g_kh [(size_t)BB*NKV*SS*HD];
__device__ __align__(16) __nv_bfloat16 g_kl [(size_t)BB*NKV*SS*HD];
__device__ __align__(16) __nv_bfloat16 g_vh [(size_t)BB*NKV*SS*HD];
__device__ __align__(16) __nv_bfloat16 g_vl [(size_t)BB*NKV*SS*HD];

// ---------------- helpers ----------------------------------------------------
__device__ __forceinline__ float ex2f(float x) {
    float y;
    asm("ex2.approx.ftz.f32 %0, %1;" : "=f"(y) : "f"(x));
    return y;
}
__device__ __forceinline__ uint32_t s2u(const void* p) {
    uint32_t r;
    asm("{ .reg .u64 t; cvta.to.shared.u64 t, %1; cvt.u32.u64 %0, t; }" : "=r"(r) : "l"(p));
    return r;
}
__device__ __forceinline__ void cp16(uint32_t dst, const void* src) {
    asm volatile("cp.async.cg.shared.global [%0], [%1], 16;" :: "r"(dst), "l"(src));
}
// bf16x2 pack: high half = hi, low half = lo
__device__ __forceinline__ uint32_t cvt2(float hi, float lo) {
    uint32_t r;
    asm("cvt.rn.bf16x2.f32 %0, %1, %2;" : "=r"(r) : "f"(hi), "f"(lo));
    return r;
}
__device__ __forceinline__ float lo_f(uint32_t u) { return __uint_as_float(u << 16); }
__device__ __forceinline__ float hi_f(uint32_t u) { return __uint_as_float(u & 0xffff0000u); }
// fp16x2 pack: low half = lo
__device__ __forceinline__ uint32_t pack_h2(float lo, float hi) {
    __half2 h = __floats2half2_rn(lo, hi);
    return *reinterpret_cast<uint32_t*>(&h);
}

#define LDSM4(r, addr) \
    asm volatile("ldmatrix.sync.aligned.m8n8.x4.shared.b16 {%0,%1,%2,%3}, [%4];" \
        : "=r"((r)[0]), "=r"((r)[1]), "=r"((r)[2]), "=r"((r)[3]) : "r"(addr))
#define LDSM4T(r, addr) \
    asm volatile("ldmatrix.sync.aligned.m8n8.x4.trans.shared.b16 {%0,%1,%2,%3}, [%4];" \
        : "=r"((r)[0]), "=r"((r)[1]), "=r"((r)[2]), "=r"((r)[3]) : "r"(addr))

#define MMA_BF16(d, a, b0v, b1v) \
    asm volatile("mma.sync.aligned.m16n8k16.row.col.f32.bf16.bf16.f32 " \
        "{%0,%1,%2,%3}, {%4,%5,%6,%7}, {%8,%9}, {%0,%1,%2,%3};" \
        : "+f"((d)[0]), "+f"((d)[1]), "+f"((d)[2]), "+f"((d)[3]) \
        : "r"((a)[0]), "r"((a)[1]), "r"((a)[2]), "r"((a)[3]), "r"(b0v), "r"(b1v))
#define MMA_F16(d, a, b0v, b1v) \
    asm volatile("mma.sync.aligned.m16n8k16.row.col.f32.f16.f16.f32 " \
        "{%0,%1,%2,%3}, {%4,%5,%6,%7}, {%8,%9}, {%0,%1,%2,%3};" \
        : "+f"((d)[0]), "+f"((d)[1]), "+f"((d)[2]), "+f"((d)[3]) \
        : "r"((a)[0]), "r"((a)[1]), "r"((a)[2]), "r"((a)[3]), "r"(b0v), "r"(b1v))

// ---------------- converters --------------------------------------------------
__global__ void __launch_bounds__(256) to_half(const float4* __restrict__ src,
                                               uint2* __restrict__ dst, int n4)
{
    int i = blockIdx.x * 256 + threadIdx.x;
    if (i >= n4) return;
    float4 v = src[i];
    dst[i] = make_uint2(pack_h2(v.x, v.y), pack_h2(v.z, v.w));
}

__global__ void __launch_bounds__(256) split_bf16(const float4* __restrict__ src,
                                                  uint2* __restrict__ hi,
                                                  uint2* __restrict__ lo,
                                                  int n4)
{
    int i = blockIdx.x * 256 + threadIdx.x;
    if (i >= n4) return;
    float4 v = src[i];
    uint32_t h01 = cvt2(v.y, v.x);
    uint32_t h23 = cvt2(v.w, v.z);
    uint32_t l01 = cvt2(v.y - hi_f(h01), v.x - lo_f(h01));
    uint32_t l23 = cvt2(v.w - hi_f(h23), v.z - lo_f(h23));
    hi[i] = make_uint2(h01, h23);
    lo[i] = make_uint2(l01, l23);
}

// ---------------- fp16 1-pass GEMM: C[M,N] = A[M,K]*B[N,K]^T (f32 acc) -------
#define HSTG   10240
#define HSTAGE (2*HSTG)
#define HGSMEM (2*HSTAGE)            // 40960

__global__ void __launch_bounds__(256) gemm_f16(
    const __half* __restrict__ Ah, const __half* __restrict__ Bh,
    float* __restrict__ C, int N, int K)
{
    extern __shared__ __align__(16) char smg[];
    const uint32_t sb = s2u(smg);
    const int tid  = threadIdx.x;
    const int lane = tid & 31;
    const int wid  = tid >> 5;
    const int wr   = wid >> 2;
    const int wc   = wid & 3;
    const int bm   = blockIdx.y << 7;
    const int bn   = blockIdx.x << 7;
    const int nk   = K >> 5;

    float acc[4][4][4];
    #pragma unroll
    for (int i = 0; i < 4; i++)
        #pragma unroll
        for (int j = 0; j < 4; j++)
            #pragma unroll
            for (int r = 0; r < 4; r++) acc[i][j][r] = 0.f;

    const int l8     = lane & 7;
    const int rowA   = ((lane >> 3) & 1) * 8 + l8;
    const int kbyteA = ((lane >> 4) & 1) * 16;
    const int rowB   = ((lane >> 4) & 1) * 8 + l8;
    const int byteB  = ((lane >> 3) & 1) * 16;

    auto fill = [&](int s, int kc) {
        const int k0 = kc << 5;
        const uint32_t dst = sb + s * HSTAGE;
        #pragma unroll
        for (int i = 0; i < 2; i++) {
            int lin = tid + i * 256;
            int row = lin >> 2;
            int ch  = lin & 3;
            uint32_t so = row * 80 + ch * 16;
            cp16(dst +        so, Ah + (size_t)(bm + row) * K + k0 + ch * 8);
            cp16(dst + HSTG + so, Bh + (size_t)(bn + row) * K + k0 + ch * 8);
        }
    };

    fill(0, 0);
    asm volatile("cp.async.commit_group;" ::: "memory");

    for (int t = 0; t < nk; ++t) {
        if (t + 1 < nk) {
            fill((t + 1) & 1, t + 1);
            asm volatile("cp.async.commit_group;" ::: "memory");
            asm volatile("cp.async.wait_group 1;" ::: "memory");
        } else {
            asm volatile("cp.async.wait_group 0;" ::: "memory");
        }
        __syncthreads();

        const uint32_t st = sb + (t & 1) * HSTAGE;
        #pragma unroll
        for (int kh = 0; kh < 2; kh++) {
            uint32_t ah[4][4];
            #pragma unroll
            for (int mi = 0; mi < 4; mi++) {
                uint32_t aaddr = st + (uint32_t)(wr*64 + mi*16 + rowA) * 80
                               + kh*32 + kbyteA;
                LDSM4(ah[mi], aaddr);
            }
            #pragma unroll
            for (int np = 0; np < 2; np++) {
                uint32_t baddr = st + HSTG + (uint32_t)(wc*32 + np*16 + rowB) * 80
                               + kh*32 + byteB;
                uint32_t bh4[4];
                LDSM4(bh4, baddr);
                #pragma unroll
                for (int mi = 0; mi < 4; mi++) {
                    MMA_F16(acc[mi][2*np],   ah[mi], bh4[0], bh4[1]);
                    MMA_F16(acc[mi][2*np+1], ah[mi], bh4[2], bh4[3]);
                }
            }
        }
        __syncthreads();
    }

    const int er = lane >> 2;
    const int ec = (lane & 3) * 2;
    #pragma unroll
    for (int mi = 0; mi < 4; mi++) {
        #pragma unroll
        for (int nn = 0; nn < 4; nn++) {
            float* cp0 = C + (size_t)(bm + wr*64 + mi*16 + er) * N
                           + bn + wc*32 + nn*8 + ec;
            *(float2*)cp0         = make_float2(acc[mi][nn][0], acc[mi][nn][1]);
            *(float2*)(cp0 + 8*N) = make_float2(acc[mi][nn][2], acc[mi][nn][3]);
        }
    }
}

// ---------------- bf16x3 GEMM: C[M,N] = A[M,K]*B[N,K]^T (f32 acc) ------------
#define STG   10240
#define STAGE (4*STG)
#define GSMEM (2*STAGE)              // 81920

__global__ void __launch_bounds__(256) gemm_mma3(
    const __nv_bfloat16* __restrict__ Ah, const __nv_bfloat16* __restrict__ Al,
    const __nv_bfloat16* __restrict__ Bh, const __nv_bfloat16* __restrict__ Bl,
    float* __restrict__ C, int N, int K)
{
    extern __shared__ __align__(16) char smg[];
    const uint32_t sb = s2u(smg);
    const int tid  = threadIdx.x;
    const int lane = tid & 31;
    const int wid  = tid >> 5;
    const int wr   = wid >> 2;
    const int wc   = wid & 3;
    const int bm   = blockIdx.y << 7;
    const int bn   = blockIdx.x << 7;
    const int nk   = K >> 5;

    float acc[4][4][4];
    #pragma unroll
    for (int i = 0; i < 4; i++)
        #pragma unroll
        for (int j = 0; j < 4; j++)
            #pragma unroll
            for (int r = 0; r < 4; r++) acc[i][j][r] = 0.f;

    const int l8     = lane & 7;
    const int rowA   = ((lane >> 3) & 1) * 8 + l8;
    const int kbyteA = ((lane >> 4) & 1) * 16;
    const int rowB   = ((lane >> 4) & 1) * 8 + l8;
    const int byteB  = ((lane >> 3) & 1) * 16;

    auto fill = [&](int s, int kc) {
        const int k0 = kc << 5;
        const uint32_t dst = sb + s * STAGE;
        #pragma unroll
        for (int i = 0; i < 2; i++) {
            int lin = tid + i * 256;
            int row = lin >> 2;
            int ch  = lin & 3;
            uint32_t so = row * 80 + ch * 16;
            size_t ga = (size_t)(bm + row) * K + k0 + ch * 8;
            size_t gb = (size_t)(bn + row) * K + k0 + ch * 8;
            cp16(dst +           so, Ah + ga);
            cp16(dst + STG     + so, Al + ga);
            cp16(dst + 2*STG   + so, Bh + gb);
            cp16(dst + 3*STG   + so, Bl + gb);
        }
    };

    fill(0, 0);
    asm volatile("cp.async.commit_group;" ::: "memory");

    for (int t = 0; t < nk; ++t) {
        if (t + 1 < nk) {
            fill((t + 1) & 1, t + 1);
            asm volatile("cp.async.commit_group;" ::: "memory");
            asm volatile("cp.async.wait_group 1;" ::: "memory");
        } else {
            asm volatile("cp.async.wait_group 0;" ::: "memory");
        }
        __syncthreads();

        const uint32_t st = sb + (t & 1) * STAGE;
        #pragma unroll
        for (int kh = 0; kh < 2; kh++) {
            uint32_t ah[4][4], al[4][4];
            #pragma unroll
            for (int mi = 0; mi < 4; mi++) {
                uint32_t aaddr = st + (uint32_t)(wr*64 + mi*16 + rowA) * 80
                               + kh*32 + kbyteA;
                LDSM4(ah[mi], aaddr);
                LDSM4(al[mi], aaddr + STG);
            }
            #pragma unroll
            for (int np = 0; np < 2; np++) {
                uint32_t baddr = st + 2*STG + (uint32_t)(wc*32 + np*16 + rowB) * 80
                               + kh*32 + byteB;
                uint32_t bh[4], bl[4];
                LDSM4(bh, baddr);
                LDSM4(bl, baddr + STG);
                #pragma unroll
                for (int mi = 0; mi < 4; mi++) {
                    MMA_BF16(acc[mi][2*np],   ah[mi], bh[0], bh[1]);
                    MMA_BF16(acc[mi][2*np],   ah[mi], bl[0], bl[1]);
                    MMA_BF16(acc[mi][2*np],   al[mi], bh[0], bh[1]);
                    MMA_BF16(acc[mi][2*np+1], ah[mi], bh[2], bh[3]);
                    MMA_BF16(acc[mi][2*np+1], ah[mi], bl[2], bl[3]);
                    MMA_BF16(acc[mi][2*np+1], al[mi], bh[2], bh[3]);
                }
            }
        }
        __syncthreads();
    }

    const int er = lane >> 2;
    const int ec = (lane & 3) * 2;
    #pragma unroll
    for (int mi = 0; mi < 4; mi++) {
        #pragma unroll
        for (int nn = 0; nn < 4; nn++) {
            float* cp0 = C + (size_t)(bm + wr*64 + mi*16 + er) * N
                           + bn + wc*32 + nn*8 + ec;
            *(float2*)cp0         = make_float2(acc[mi][nn][0], acc[mi][nn][1]);
            *(float2*)(cp0 + 8*N) = make_float2(acc[mi][nn][2], acc[mi][nn][3]);
        }
    }
}

// ---------------- RMSNorm + RoPE + bf16 hi/lo split --------------------------
#define QSCALE 0.12751943f   // (1/sqrt(128)) * log2(e)
__global__ void __launch_bounds__(256) norm_split(const float* __restrict__ qkv,
                                                  const float* __restrict__ freqs,
                                                  const float* __restrict__ qw,
                                                  const float* __restrict__ kw,
                                                  __nv_bfloat16* __restrict__ qh,
                                                  __nv_bfloat16* __restrict__ ql,
                                                  __nv_bfloat16* __restrict__ kh,
                                                  __nv_bfloat16* __restrict__ kl,
                                                  __nv_bfloat16* __restrict__ vh,
                                                  __nv_bfloat16* __restrict__ vl)
{
    const int wid  = threadIdx.x >> 5;
    const int lane = threadIdx.x & 31;
    const int s    = blockIdx.x * 8 + wid;
    const int h    = blockIdx.y;
    const int b    = blockIdx.z;

    const float* src = qkv + ((size_t)(b*SS + s)) * QKVE + h * HD;
    float4 v = *(const float4*)(src + lane*4);
    float x0 = v.x, x1 = v.y, x2 = v.z, x3 = v.w;

    if (h < NH + NKV) {
        float ssum = x0*x0 + x1*x1 + x2*x2 + x3*x3;
        #pragma unroll
        for (int off = 16; off >= 1; off >>= 1)
            ssum += __shfl_xor_sync(0xffffffffu, ssum, off);
        const bool isq = (h < NH);
        float inv = rsqrtf(ssum * (1.0f / HD) + 1e-6f) * (isq ? QSCALE : 1.0f);
        const float* wn = isq ? qw : kw;
        float4 wv = *(const float4*)(wn + lane*4);
        float t0 = x0 * inv * wv.x;
        float t1 = x1 * inv * wv.y;
        float t2 = x2 * inv * wv.z;
        float t3 = x3 * inv * wv.w;
        float4 f = *(const float4*)(freqs + (size_t)s*128 + lane*4);
        x0 = t0*f.x - t1*f.y;
        x1 = t1*f.x + t0*f.y;
        x2 = t2*f.z - t3*f.w;
        x3 = t3*f.z + t2*f.w;
    }

    uint32_t h01 = cvt2(x1, x0);
    uint32_t h23 = cvt2(x3, x2);
    uint32_t l01 = cvt2(x1 - hi_f(h01), x0 - lo_f(h01));
    uint32_t l23 = cvt2(x3 - hi_f(h23), x2 - lo_f(h23));

    __nv_bfloat16 *dh, *dl;
    size_t row;
    if (h < NH)            { row = (size_t)(b*NH  + h)           * SS + s; dh = qh; dl = ql; }
    else if (h < NH + NKV) { row = (size_t)(b*NKV + h - NH)      * SS + s; dh = kh; dl = kl; }
    else                   { row = (size_t)(b*NKV + h - NH - NKV)* SS + s; dh = vh; dl = vl; }
    *(uint2*)(dh + row*HD + lane*4) = make_uint2(h01, h23);
    *(uint2*)(dl + row*HD + lane*4) = make_uint2(l01, l23);
}

// ---------------- Flash attention on tensor cores (bf16x3, causal, GQA) ------
#define FST 272
#define QH_OFF 0
#define QL_OFF (128*FST)
#define KH_OFF (2*128*FST)
#define KL_OFF (KH_OFF + 64*FST)
#define VH_OFF (KL_OFF + 64*FST)
#define VL_OFF (VH_OFF + 64*FST)
#define FLASH_SMEM (VL_OFF + 64*FST)    // 139264

__global__ void __launch_bounds__(256) flash_mma(
    const __nv_bfloat16* __restrict__ qh, const __nv_bfloat16* __restrict__ ql,
    const __nv_bfloat16* __restrict__ kh, const __nv_bfloat16* __restrict__ kl,
    const __nv_bfloat16* __restrict__ vh, const __nv_bfloat16* __restrict__ vl,
    __nv_bfloat16* __restrict__ Yh, __nv_bfloat16* __restrict__ Yl)
{
    extern __shared__ __align__(16) char smf[];
    const uint32_t sb = s2u(smf);
    const int tid  = threadIdx.x;
    const int lane = tid & 31;
    const int wid  = tid >> 5;
    const int qb   = gridDim.x - 1 - blockIdx.x;
    const int h    = blockIdx.y;
    const int b    = blockIdx.z;
    const int q0   = qb * 128;
    const int hkv  = h >> 2;
    const int mrow = wid * 16;

    const __nv_bfloat16* qhp = qh + ((size_t)(b*NH  + h  ) * SS + q0) * HD;
    const __nv_bfloat16* qlp = ql + ((size_t)(b*NH  + h  ) * SS + q0) * HD;
    const __nv_bfloat16* khp = kh + ((size_t)(b*NKV + hkv) * SS) * HD;
    const __nv_bfloat16* klp = kl + ((size_t)(b*NKV + hkv) * SS) * HD;
    const __nv_bfloat16* vhp = vh + ((size_t)(b*NKV + hkv) * SS) * HD;
    const __nv_bfloat16* vlp = vl + ((size_t)(b*NKV + hkv) * SS) * HD;

    #pragma unroll
    for (int i = 0; i < 8; i++) {
        int lin = tid + i*256;
        int r   = lin >> 4;
        int ch  = lin & 15;
        cp16(sb + QH_OFF + r*FST + ch*16, qhp + (size_t)r*HD + ch*8);
        cp16(sb + QL_OFF + r*FST + ch*16, qlp + (size_t)r*HD + ch*8);
    }

    const int l8 = lane & 7;
    const int rA = ((lane >> 3) & 1) * 8 + l8;
    const int cA = ((lane >> 4) & 1) * 16;
    const int rB = ((lane >> 4) & 1) * 8 + l8;
    const int cB = ((lane >> 3) & 1) * 16;
    const int lr = lane >> 2;
    const int l4 = lane & 3;

    float O[16][4];
    #pragma unroll
    for (int j = 0; j < 16; j++)
        #pragma unroll
        for (int r = 0; r < 4; r++) O[j][r] = 0.f;
    float m0v = -1e30f, m1v = -1e30f, l0v = 0.f, l1v = 0.f;

    const int nkb = 2*qb + 2;
    for (int kb = 0; kb < nkb; ++kb) {
        const int k0 = kb * 64;
        if (kb) __syncthreads();
        #pragma unroll
        for (int i = 0; i < 4; i++) {
            int lin = tid + i*256;
            int r   = lin >> 4;
            int ch  = lin & 15;
            size_t g = (size_t)(k0 + r)*HD + ch*8;
            uint32_t so = r*FST + ch*16;
            cp16(sb + KH_OFF + so, khp + g);
            cp16(sb + KL_OFF + so, klp + g);
            cp16(sb + VH_OFF + so, vhp + g);
            cp16(sb + VL_OFF + so, vlp + g);
        }
        asm volatile("cp.async.commit_group;" ::: "memory");
        asm volatile("cp.async.wait_group 0;" ::: "memory");
        __syncthreads();

        float S[8][4];
        #pragma unroll
        for (int j = 0; j < 8; j++)
            #pragma unroll
            for (int r = 0; r < 4; r++) S[j][r] = 0.f;

        #pragma unroll
        for (int kc = 0; kc < 8; kc++) {
            uint32_t qa_h[4], qa_l[4];
            uint32_t qaddr = sb + QH_OFF + (uint32_t)(mrow + rA)*FST + kc*32 + cA;
            LDSM4(qa_h, qaddr);
            LDSM4(qa_l, qaddr + (QL_OFF - QH_OFF));
            #pragma unroll
            for (int ng = 0; ng < 4; ng++) {
                uint32_t kaddr = sb + KH_OFF + (uint32_t)(ng*16 + rB)*FST + kc*32 + cB;
                uint32_t bh4[4], bl4[4];
                LDSM4(bh4, kaddr);
                LDSM4(bl4, kaddr + (KL_OFF - KH_OFF));
                MMA_BF16(S[2*ng],   qa_h, bh4[0], bh4[1]);
                MMA_BF16(S[2*ng],   qa_h, bl4[0], bl4[1]);
                MMA_BF16(S[2*ng],   qa_l, bh4[0], bh4[1]);
                MMA_BF16(S[2*ng+1], qa_h, bh4[2], bh4[3]);
                MMA_BF16(S[2*ng+1], qa_h, bl4[2], bl4[3]);
                MMA_BF16(S[2*ng+1], qa_l, bh4[2], bh4[3]);
            }
        }

        if (kb >= 2*qb) {
            int row0 = q0 + mrow + lr;
            int row1 = row0 + 8;
            #pragma unroll
            for (int j = 0; j < 8; j++) {
                int c0 = k0 + 8*j + 2*l4;
                if (c0     > row0) S[j][0] = -1e30f;
                if (c0 + 1 > row0) S[j][1] = -1e30f;
                if (c0     > row1) S[j][2] = -1e30f;
                if (c0 + 1 > row1) S[j][3] = -1e30f;
            }
        }

        {
            float mx = -1e30f;
            #pragma unroll
            for (int j = 0; j < 8; j++) mx = fmaxf(mx, fmaxf(S[j][0], S[j][1]));
            mx = fmaxf(mx, __shfl_xor_sync(0xffffffffu, mx, 1));
            mx = fmaxf(mx, __shfl_xor_sync(0xffffffffu, mx, 2));
            float mn = fmaxf(m0v, mx);
            float corr = ex2f(m0v - mn);
            m0v = mn;
            float rs = 0.f;
            #pragma unroll
            for (int j = 0; j < 8; j++) {
                S[j][0] = ex2f(S[j][0] - mn);
                S[j][1] = ex2f(S[j][1] - mn);
                rs += S[j][0] + S[j][1];
            }
            rs += __shfl_xor_sync(0xffffffffu, rs, 1);
            rs += __shfl_xor_sync(0xffffffffu, rs, 2);
            l0v = l0v * corr + rs;
            #pragma unroll
            for (int j = 0; j < 16; j++) { O[j][0] *= corr; O[j][1] *= corr; }
        }
        {
            float mx = -1e30f;
            #pragma unroll
            for (int j = 0; j < 8; j++) mx = fmaxf(mx, fmaxf(S[j][2], S[j][3]));
            mx = fmaxf(mx, __shfl_xor_sync(0xffffffffu, mx, 1));
            mx = fmaxf(mx, __shfl_xor_sync(0xffffffffu, mx, 2));
            float mn = fmaxf(m1v, mx);
            float corr = ex2f(m1v - mn);
            m1v = mn;
            float rs = 0.f;
            #pragma unroll
            for (int j = 0; j < 8; j++) {
                S[j][2] = ex2f(S[j][2] - mn);
                S[j][3] = ex2f(S[j][3] - mn);
                rs += S[j][2] + S[j][3];
            }
            rs += __shfl_xor_sync(0xffffffffu, rs, 1);
            rs += __shfl_xor_sync(0xffffffffu, rs, 2);
            l1v = l1v * corr + rs;
            #pragma unroll
            for (int j = 0; j < 16; j++) { O[j][2] *= corr; O[j][3] *= corr; }
        }

        #pragma unroll
        for (int t = 0; t < 4; t++) {
            uint32_t Ahf[4], Alf[4];
            Ahf[0] = cvt2(S[2*t][1],   S[2*t][0]);
            Ahf[1] = cvt2(S[2*t][3],   S[2*t][2]);
            Ahf[2] = cvt2(S[2*t+1][1], S[2*t+1][0]);
            Ahf[3] = cvt2(S[2*t+1][3], S[2*t+1][2]);
            Alf[0] = cvt2(S[2*t][1]   - hi_f(Ahf[0]), S[2*t][0]   - lo_f(Ahf[0]));
            Alf[1] = cvt2(S[2*t][3]   - hi_f(Ahf[1]), S[2*t][2]   - lo_f(Ahf[1]));
            Alf[2] = cvt2(S[2*t+1][1] - hi_f(Ahf[2]), S[2*t+1][0] - lo_f(Ahf[2]));
            Alf[3] = cvt2(S[2*t+1][3] - hi_f(Ahf[3]), S[2*t+1][2] - lo_f(Ahf[3]));
            #pragma unroll
            for (int dg = 0; dg < 8; dg++) {
                uint32_t vaddr = sb + VH_OFF + (uint32_t)(t*16 + rA)*FST + dg*32 + cA;
                uint32_t vhf[4], vlf[4];
                LDSM4T(vhf, vaddr);
                LDSM4T(vlf, vaddr + (VL_OFF - VH_OFF));
                MMA_BF16(O[2*dg],   Ahf, vhf[0], vhf[1]);
                MMA_BF16(O[2*dg],   Ahf, vlf[0], vlf[1]);
                MMA_BF16(O[2*dg],   Alf, vhf[0], vhf[1]);
                MMA_BF16(O[2*dg+1], Ahf, vhf[2], vhf[3]);
                MMA_BF16(O[2*dg+1], Ahf, vlf[2], vlf[3]);
                MMA_BF16(O[2*dg+1], Alf, vhf[2], vhf[3]);
            }
        }
    }

    // ---- write O as bf16 hi/lo (feeds out-projection directly) ----
    float inv0 = 1.0f / l0v;
    float inv1 = 1.0f / l1v;
    int row0 = q0 + mrow + lr;
    size_t base0 = (size_t)(b*SS + row0) * DD + h*HD;
    size_t base1 = base0 + (size_t)8 * DD;
    #pragma unroll
    for (int j = 0; j < 16; j++) {
        float a0 = O[j][0]*inv0, a1 = O[j][1]*inv0;
        float b0 = O[j][2]*inv1, b1 = O[j][3]*inv1;
        uint32_t h0 = cvt2(a1, a0);
        uint32_t l0 = cvt2(a1 - hi_f(h0), a0 - lo_f(h0));
        uint32_t h1 = cvt2(b1, b0);
        uint32_t l1 = cvt2(b1 - hi_f(h1), b0 - lo_f(h1));
        *(uint32_t*)(Yh + base0 + 8*j + 2*l4) = h0;
        *(uint32_t*)(Yl + base0 + 8*j + 2*l4) = l0;
        *(uint32_t*)(Yh + base1 + 8*j + 2*l4) = h1;
        *(uint32_t*)(Yl + base1 + 8*j + 2*l4) = l1;
    }
}

// ---------------- launch ----------------------------------------------------
extern "C" void kernel_launch(void* const* d_in, const int* in_sizes, int n_in,
                              void* d_out, int out_size)
{
    const float* x     = (const float*)d_in[0];
    const float* freqs = (const float*)d_in[1];
    const float* wqkv  = (const float*)d_in[2];
    const float* wo    = (const float*)d_in[3];
    const float* qw    = (const float*)d_in[4];
    const float* kw    = (const float*)d_in[5];
    float* out = (float*)d_out;

    float *p_qkv;
    __half *p_xh, *p_wqh;
    __nv_bfloat16 *p_woh, *p_wol, *p_yh, *p_yl;
    __nv_bfloat16 *p_qh, *p_ql, *p_kh, *p_kl, *p_vh, *p_vl;
    cudaGetSymbolAddress((void**)&p_qkv, g_qkv);
    cudaGetSymbolAddress((void**)&p_xh,  g_xh);
    cudaGetSymbolAddress((void**)&p_wqh, g_wqh);
    cudaGetSymbolAddress((void**)&p_woh, g_woh);
    cudaGetSymbolAddress((void**)&p_wol, g_wol);
    cudaGetSymbolAddress((void**)&p_yh,  g_yh);
    cudaGetSymbolAddress((void**)&p_yl,  g_yl);
    cudaGetSymbolAddress((void**)&p_qh,  g_qh);
    cudaGetSymbolAddress((void**)&p_ql,  g_ql);
    cudaGetSymbolAddress((void**)&p_kh,  g_kh);
    cudaGetSymbolAddress((void**)&p_kl,  g_kl);
    cudaGetSymbolAddress((void**)&p_vh,  g_vh);
    cudaGetSymbolAddress((void**)&p_vl,  g_vl);

    cudaFuncSetAttribute(gemm_f16,
                         cudaFuncAttributeMaxDynamicSharedMemorySize, HGSMEM);
    cudaFuncSetAttribute(gemm_mma3,
                         cudaFuncAttributeMaxDynamicSharedMemorySize, GSMEM);
    cudaFuncSetAttribute(flash_mma,
                         cudaFuncAttributeMaxDynamicSharedMemorySize, FLASH_SMEM);

    const int n4_x  = BB*SS*DD / 4;
    const int n4_wq = QKVE*DD  / 4;
    const int n4_wo = DD*DD    / 4;

    // 0) converts: x & wqkv -> fp16 (QKV proj); wo -> bf16 hi/lo (out proj)
    to_half<<<n4_x /256, 256>>>((const float4*)x,    (uint2*)p_xh,  n4_x);
    to_half<<<n4_wq/256, 256>>>((const float4*)wqkv, (uint2*)p_wqh, n4_wq);
    split_bf16<<<n4_wo/256, 256>>>((const float4*)wo, (uint2*)p_woh, (uint2*)p_wol, n4_wo);

    // 1) QKV projection (fp16 1-pass tensor cores)
    gemm_f16<<<dim3(QKVE/128, (BB*SS)/128), 256, HGSMEM>>>(
        p_xh, p_wqh, p_qkv, QKVE, DD);

    // 2) RMSNorm + RoPE + bf16 hi/lo split (Q pre-scaled by scale*log2e)
    norm_split<<<dim3(SS/8, EHEADS, BB), 256>>>(p_qkv, freqs, qw, kw,
                                                p_qh, p_ql, p_kh, p_kl, p_vh, p_vl);

    // 3) Flash attention (bf16x3 tensor cores); writes y as bf16 hi/lo
    flash_mma<<<dim3(SS/128, NH, BB), 256, FLASH_SMEM>>>(
        p_qh, p_ql, p_kh, p_kl, p_vh, p_vl, p_yh, p_yl);

    // 4) Output projection (bf16x3 tensor cores)
    gemm_mma3<<<dim3(DD/128, (BB*SS)/128), 256, GSMEM>>>(
        p_yh, p_yl, p_woh, p_wol, out, DD, NH*HD);
}

// round 12
// speedup vs baseline: 2.9453x; 1.0185x over previous
#include <cuda_runtime.h>
#include <cuda_fp16.h>
#include <cuda_bf16.h>
#include <math.h>
#include <stdint.h>

// Problem constants
#define BB   2
#define SS   2048
#define DD   2048
#define NH   16
#define NKV  4
#define HD   128
#define EHEADS (NH + 2*NKV)          // 24
#define QKVE (EHEADS * HD)           // 3072

// ---------------- scratch (device globals; no allocation allowed) ----------
__device__ __align__(16) float g_qkv[(size_t)BB * SS * QKVE];
// fp16 operands (QKV projection only)
__device__ __align__(16) __half g_xh [(size_t)BB*SS*DD];
__device__ __align__(16) __half g_wqh[(size_t)QKVE*DD];
// bf16 split operands (out projection + flash)
__device__ __align__(16) __nv_bfloat16 g_woh[(size_t)DD*DD];
__device__ __align__(16) __nv_bfloat16 g_wol[(size_t)DD*DD];
__device__ __align__(16) __nv_bfloat16 g_yh [(size_t)BB*SS*DD];
__device__ __align__(16) __nv_bfloat16 g_yl [(size_t)BB*SS*DD];
__device__ __align__(16) __nv_bfloat16 g_qh [(size_t)BB*NH *SS*HD];
__device__ __align__(16) __nv_bfloat16 g_ql [(size_t)BB*NH *SS*HD];
__device__ __align__(16) __nv_bfloat16 g_kh [(size_t)BB*NKV*SS*HD];
__device__ __align__(16) __nv_bfloat16 g_kl [(size_t)BB*NKV*SS*HD];
__device__ __align__(16) __nv_bfloat16 g_vh [(size_t)BB*NKV*SS*HD];
__device__ __align__(16) __nv_bfloat16 g_vl [(size_t)BB*NKV*SS*HD];

// ---------------- helpers ----------------------------------------------------
__device__ __forceinline__ float ex2f(float x) {
    float y;
    asm("ex2.approx.ftz.f32 %0, %1;" : "=f"(y) : "f"(x));
    return y;
}
__device__ __forceinline__ uint32_t s2u(const void* p) {
    uint32_t r;
    asm("{ .reg .u64 t; cvta.to.shared.u64 t, %1; cvt.u32.u64 %0, t; }" : "=r"(r) : "l"(p));
    return r;
}
__device__ __forceinline__ void cp16(uint32_t dst, const void* src) {
    asm volatile("cp.async.cg.shared.global [%0], [%1], 16;" :: "r"(dst), "l"(src));
}
__device__ __forceinline__ uint32_t cvt2(float hi, float lo) {
    uint32_t r;
    asm("cvt.rn.bf16x2.f32 %0, %1, %2;" : "=r"(r) : "f"(hi), "f"(lo));
    return r;
}
__device__ __forceinline__ float lo_f(uint32_t u) { return __uint_as_float(u << 16); }
__device__ __forceinline__ float hi_f(uint32_t u) { return __uint_as_float(u & 0xffff0000u); }
__device__ __forceinline__ uint32_t pack_h2(float lo, float hi) {
    __half2 h = __floats2half2_rn(lo, hi);
    return *reinterpret_cast<uint32_t*>(&h);
}

#define LDSM4(r, addr) \
    asm volatile("ldmatrix.sync.aligned.m8n8.x4.shared.b16 {%0,%1,%2,%3}, [%4];" \
        : "=r"((r)[0]), "=r"((r)[1]), "=r"((r)[2]), "=r"((r)[3]) : "r"(addr))
#define LDSM4T(r, addr) \
    asm volatile("ldmatrix.sync.aligned.m8n8.x4.trans.shared.b16 {%0,%1,%2,%3}, [%4];" \
        : "=r"((r)[0]), "=r"((r)[1]), "=r"((r)[2]), "=r"((r)[3]) : "r"(addr))

#define MMA_BF16(d, a, b0v, b1v) \
    asm volatile("mma.sync.aligned.m16n8k16.row.col.f32.bf16.bf16.f32 " \
        "{%0,%1,%2,%3}, {%4,%5,%6,%7}, {%8,%9}, {%0,%1,%2,%3};" \
        : "+f"((d)[0]), "+f"((d)[1]), "+f"((d)[2]), "+f"((d)[3]) \
        : "r"((a)[0]), "r"((a)[1]), "r"((a)[2]), "r"((a)[3]), "r"(b0v), "r"(b1v))
#define MMA_F16(d, a, b0v, b1v) \
    asm volatile("mma.sync.aligned.m16n8k16.row.col.f32.f16.f16.f32 " \
        "{%0,%1,%2,%3}, {%4,%5,%6,%7}, {%8,%9}, {%0,%1,%2,%3};" \
        : "+f"((d)[0]), "+f"((d)[1]), "+f"((d)[2]), "+f"((d)[3]) \
        : "r"((a)[0]), "r"((a)[1]), "r"((a)[2]), "r"((a)[3]), "r"(b0v), "r"(b1v))

// ---------------- converters --------------------------------------------------
__global__ void __launch_bounds__(256) to_half(const float4* __restrict__ src,
                                               uint2* __restrict__ dst, int n4)
{
    int i = blockIdx.x * 256 + threadIdx.x;
    if (i >= n4) return;
    float4 v = src[i];
    dst[i] = make_uint2(pack_h2(v.x, v.y), pack_h2(v.z, v.w));
}

__global__ void __launch_bounds__(256) split_bf16(const float4* __restrict__ src,
                                                  uint2* __restrict__ hi,
                                                  uint2* __restrict__ lo,
                                                  int n4)
{
    int i = blockIdx.x * 256 + threadIdx.x;
    if (i >= n4) return;
    float4 v = src[i];
    uint32_t h01 = cvt2(v.y, v.x);
    uint32_t h23 = cvt2(v.w, v.z);
    uint32_t l01 = cvt2(v.y - hi_f(h01), v.x - lo_f(h01));
    uint32_t l23 = cvt2(v.w - hi_f(h23), v.z - lo_f(h23));
    hi[i] = make_uint2(h01, h23);
    lo[i] = make_uint2(l01, l23);
}

// ---------------- fp16 1-pass GEMM, 3-stage pipeline, 1 sync/chunk ----------
#define HSTG   10240
#define HSTAGE (2*HSTG)
#define HGSMEM (3*HSTAGE)            // 61440

__global__ void __launch_bounds__(256) gemm_f16(
    const __half* __restrict__ Ah, const __half* __restrict__ Bh,
    float* __restrict__ C, int N, int K)
{
    extern __shared__ __align__(16) char smg[];
    const uint32_t sb = s2u(smg);
    const int tid  = threadIdx.x;
    const int lane = tid & 31;
    const int wid  = tid >> 5;
    const int wr   = wid >> 2;
    const int wc   = wid & 3;
    const int bm   = blockIdx.y << 7;
    const int bn   = blockIdx.x << 7;
    const int nk   = K >> 5;

    float acc[4][4][4];
    #pragma unroll
    for (int i = 0; i < 4; i++)
        #pragma unroll
        for (int j = 0; j < 4; j++)
            #pragma unroll
            for (int r = 0; r < 4; r++) acc[i][j][r] = 0.f;

    const int l8     = lane & 7;
    const int rowA   = ((lane >> 3) & 1) * 8 + l8;
    const int kbyteA = ((lane >> 4) & 1) * 16;
    const int rowB   = ((lane >> 4) & 1) * 8 + l8;
    const int byteB  = ((lane >> 3) & 1) * 16;

    auto fill = [&](int s, int kc) {
        const int k0 = kc << 5;
        const uint32_t dst = sb + s * HSTAGE;
        #pragma unroll
        for (int i = 0; i < 2; i++) {
            int lin = tid + i * 256;
            int row = lin >> 2;
            int ch  = lin & 3;
            uint32_t so = row * 80 + ch * 16;
            cp16(dst +        so, Ah + (size_t)(bm + row) * K + k0 + ch * 8);
            cp16(dst + HSTG + so, Bh + (size_t)(bn + row) * K + k0 + ch * 8);
        }
        asm volatile("cp.async.commit_group;" ::: "memory");
    };

    fill(0, 0);
    if (nk > 1) fill(1, 1);

    for (int t = 0; t < nk; ++t) {
        if (t + 1 < nk) asm volatile("cp.async.wait_group 1;" ::: "memory");
        else            asm volatile("cp.async.wait_group 0;" ::: "memory");
        __syncthreads();   // all warps past compute(t-1); fill(t) visible

        if (t + 2 < nk) fill((t + 2) % 3, t + 2);   // writes stage (t-1)%3: safe

        const uint32_t st = sb + (t % 3) * HSTAGE;
        #pragma unroll
        for (int kh = 0; kh < 2; kh++) {
            uint32_t ah[4][4];
            #pragma unroll
            for (int mi = 0; mi < 4; mi++) {
                uint32_t aaddr = st + (uint32_t)(wr*64 + mi*16 + rowA) * 80
                               + kh*32 + kbyteA;
                LDSM4(ah[mi], aaddr);
            }
            #pragma unroll
            for (int np = 0; np < 2; np++) {
                uint32_t baddr = st + HSTG + (uint32_t)(wc*32 + np*16 + rowB) * 80
                               + kh*32 + byteB;
                uint32_t bh4[4];
                LDSM4(bh4, baddr);
                #pragma unroll
                for (int mi = 0; mi < 4; mi++) {
                    MMA_F16(acc[mi][2*np],   ah[mi], bh4[0], bh4[1]);
                    MMA_F16(acc[mi][2*np+1], ah[mi], bh4[2], bh4[3]);
                }
            }
        }
    }

    const int er = lane >> 2;
    const int ec = (lane & 3) * 2;
    #pragma unroll
    for (int mi = 0; mi < 4; mi++) {
        #pragma unroll
        for (int nn = 0; nn < 4; nn++) {
            float* cp0 = C + (size_t)(bm + wr*64 + mi*16 + er) * N
                           + bn + wc*32 + nn*8 + ec;
            *(float2*)cp0         = make_float2(acc[mi][nn][0], acc[mi][nn][1]);
            *(float2*)(cp0 + 8*N) = make_float2(acc[mi][nn][2], acc[mi][nn][3]);
        }
    }
}

// ---------------- bf16x3 GEMM (2-stage, unchanged) ---------------------------
#define STG   10240
#define STAGE (4*STG)
#define GSMEM (2*STAGE)              // 81920

__global__ void __launch_bounds__(256) gemm_mma3(
    const __nv_bfloat16* __restrict__ Ah, const __nv_bfloat16* __restrict__ Al,
    const __nv_bfloat16* __restrict__ Bh, const __nv_bfloat16* __restrict__ Bl,
    float* __restrict__ C, int N, int K)
{
    extern __shared__ __align__(16) char smg[];
    const uint32_t sb = s2u(smg);
    const int tid  = threadIdx.x;
    const int lane = tid & 31;
    const int wid  = tid >> 5;
    const int wr   = wid >> 2;
    const int wc   = wid & 3;
    const int bm   = blockIdx.y << 7;
    const int bn   = blockIdx.x << 7;
    const int nk   = K >> 5;

    float acc[4][4][4];
    #pragma unroll
    for (int i = 0; i < 4; i++)
        #pragma unroll
        for (int j = 0; j < 4; j++)
            #pragma unroll
            for (int r = 0; r < 4; r++) acc[i][j][r] = 0.f;

    const int l8     = lane & 7;
    const int rowA   = ((lane >> 3) & 1) * 8 + l8;
    const int kbyteA = ((lane >> 4) & 1) * 16;
    const int rowB   = ((lane >> 4) & 1) * 8 + l8;
    const int byteB  = ((lane >> 3) & 1) * 16;

    auto fill = [&](int s, int kc) {
        const int k0 = kc << 5;
        const uint32_t dst = sb + s * STAGE;
        #pragma unroll
        for (int i = 0; i < 2; i++) {
            int lin = tid + i * 256;
            int row = lin >> 2;
            int ch  = lin & 3;
            uint32_t so = row * 80 + ch * 16;
            size_t ga = (size_t)(bm + row) * K + k0 + ch * 8;
            size_t gb = (size_t)(bn + row) * K + k0 + ch * 8;
            cp16(dst +           so, Ah + ga);
            cp16(dst + STG     + so, Al + ga);
            cp16(dst + 2*STG   + so, Bh + gb);
            cp16(dst + 3*STG   + so, Bl + gb);
        }
    };

    fill(0, 0);
    asm volatile("cp.async.commit_group;" ::: "memory");

    for (int t = 0; t < nk; ++t) {
        if (t + 1 < nk) {
            fill((t + 1) & 1, t + 1);
            asm volatile("cp.async.commit_group;" ::: "memory");
            asm volatile("cp.async.wait_group 1;" ::: "memory");
        } else {
            asm volatile("cp.async.wait_group 0;" ::: "memory");
        }
        __syncthreads();

        const uint32_t st = sb + (t & 1) * STAGE;
        #pragma unroll
        for (int kh = 0; kh < 2; kh++) {
            uint32_t ah[4][4], al[4][4];
            #pragma unroll
            for (int mi = 0; mi < 4; mi++) {
                uint32_t aaddr = st + (uint32_t)(wr*64 + mi*16 + rowA) * 80
                               + kh*32 + kbyteA;
                LDSM4(ah[mi], aaddr);
                LDSM4(al[mi], aaddr + STG);
            }
            #pragma unroll
            for (int np = 0; np < 2; np++) {
                uint32_t baddr = st + 2*STG + (uint32_t)(wc*32 + np*16 + rowB) * 80
                               + kh*32 + byteB;
                uint32_t bh[4], bl[4];
                LDSM4(bh, baddr);
                LDSM4(bl, baddr + STG);
                #pragma unroll
                for (int mi = 0; mi < 4; mi++) {
                    MMA_BF16(acc[mi][2*np],   ah[mi], bh[0], bh[1]);
                    MMA_BF16(acc[mi][2*np],   ah[mi], bl[0], bl[1]);
                    MMA_BF16(acc[mi][2*np],   al[mi], bh[0], bh[1]);
                    MMA_BF16(acc[mi][2*np+1], ah[mi], bh[2], bh[3]);
                    MMA_BF16(acc[mi][2*np+1], ah[mi], bl[2], bl[3]);
                    MMA_BF16(acc[mi][2*np+1], al[mi], bh[2], bh[3]);
                }
            }
        }
        __syncthreads();
    }

    const int er = lane >> 2;
    const int ec = (lane & 3) * 2;
    #pragma unroll
    for (int mi = 0; mi < 4; mi++) {
        #pragma unroll
        for (int nn = 0; nn < 4; nn++) {
            float* cp0 = C + (size_t)(bm + wr*64 + mi*16 + er) * N
                           + bn + wc*32 + nn*8 + ec;
            *(float2*)cp0         = make_float2(acc[mi][nn][0], acc[mi][nn][1]);
            *(float2*)(cp0 + 8*N) = make_float2(acc[mi][nn][2], acc[mi][nn][3]);
        }
    }
}

// ---------------- RMSNorm + RoPE + bf16 hi/lo split --------------------------
#define QSCALE 0.12751943f   // (1/sqrt(128)) * log2(e)
__global__ void __launch_bounds__(256) norm_split(const float* __restrict__ qkv,
                                                  const float* __restrict__ freqs,
                                                  const float* __restrict__ qw,
                                                  const float* __restrict__ kw,
                                                  __nv_bfloat16* __restrict__ qh,
                                                  __nv_bfloat16* __restrict__ ql,
                                                  __nv_bfloat16* __restrict__ kh,
                                                  __nv_bfloat16* __restrict__ kl,
                                                  __nv_bfloat16* __restrict__ vh,
                                                  __nv_bfloat16* __restrict__ vl)
{
    const int wid  = threadIdx.x >> 5;
    const int lane = threadIdx.x & 31;
    const int s    = blockIdx.x * 8 + wid;
    const int h    = blockIdx.y;
    const int b    = blockIdx.z;

    const float* src = qkv + ((size_t)(b*SS + s)) * QKVE + h * HD;
    float4 v = *(const float4*)(src + lane*4);
    float x0 = v.x, x1 = v.y, x2 = v.z, x3 = v.w;

    if (h < NH + NKV) {
        float ssum = x0*x0 + x1*x1 + x2*x2 + x3*x3;
        #pragma unroll
        for (int off = 16; off >= 1; off >>= 1)
            ssum += __shfl_xor_sync(0xffffffffu, ssum, off);
        const bool isq = (h < NH);
        float inv = rsqrtf(ssum * (1.0f / HD) + 1e-6f) * (isq ? QSCALE : 1.0f);
        const float* wn = isq ? qw : kw;
        float4 wv = *(const float4*)(wn + lane*4);
        float t0 = x0 * inv * wv.x;
        float t1 = x1 * inv * wv.y;
        float t2 = x2 * inv * wv.z;
        float t3 = x3 * inv * wv.w;
        float4 f = *(const float4*)(freqs + (size_t)s*128 + lane*4);
        x0 = t0*f.x - t1*f.y;
        x1 = t1*f.x + t0*f.y;
        x2 = t2*f.z - t3*f.w;
        x3 = t3*f.z + t2*f.w;
    }

    uint32_t h01 = cvt2(x1, x0);
    uint32_t h23 = cvt2(x3, x2);
    uint32_t l01 = cvt2(x1 - hi_f(h01), x0 - lo_f(h01));
    uint32_t l23 = cvt2(x3 - hi_f(h23), x2 - lo_f(h23));

    __nv_bfloat16 *dh, *dl;
    size_t row;
    if (h < NH)            { row = (size_t)(b*NH  + h)           * SS + s; dh = qh; dl = ql; }
    else if (h < NH + NKV) { row = (size_t)(b*NKV + h - NH)      * SS + s; dh = kh; dl = kl; }
    else                   { row = (size_t)(b*NKV + h - NH - NKV)* SS + s; dh = vh; dl = vl; }
    *(uint2*)(dh + row*HD + lane*4) = make_uint2(h01, h23);
    *(uint2*)(dl + row*HD + lane*4) = make_uint2(l01, l23);
}

// ---------------- Flash attention (bf16x3) — double-buffered K/V -------------
#define FST 272
#define QH_OFF 0
#define QL_OFF (128*FST)
#define KV_OFF (2*128*FST)              // 69632
#define KVSPL  (64*FST)                 // 17408: KH->KL->VH->VL spacing
#define KVSTAGE (4*KVSPL)               // 69632 per stage
#define FLASH_SMEM (KV_OFF + 2*KVSTAGE) // 208896

__global__ void __launch_bounds__(256) flash_mma(
    const __nv_bfloat16* __restrict__ qh, const __nv_bfloat16* __restrict__ ql,
    const __nv_bfloat16* __restrict__ kh, const __nv_bfloat16* __restrict__ kl,
    const __nv_bfloat16* __restrict__ vh, const __nv_bfloat16* __restrict__ vl,
    __nv_bfloat16* __restrict__ Yh, __nv_bfloat16* __restrict__ Yl)
{
    extern __shared__ __align__(16) char smf[];
    const uint32_t sb = s2u(smf);
    const int tid  = threadIdx.x;
    const int lane = tid & 31;
    const int wid  = tid >> 5;
    const int qb   = gridDim.x - 1 - blockIdx.x;
    const int h    = blockIdx.y;
    const int b    = blockIdx.z;
    const int q0   = qb * 128;
    const int hkv  = h >> 2;
    const int mrow = wid * 16;

    const __nv_bfloat16* qhp = qh + ((size_t)(b*NH  + h  ) * SS + q0) * HD;
    const __nv_bfloat16* qlp = ql + ((size_t)(b*NH  + h  ) * SS + q0) * HD;
    const __nv_bfloat16* khp = kh + ((size_t)(b*NKV + hkv) * SS) * HD;
    const __nv_bfloat16* klp = kl + ((size_t)(b*NKV + hkv) * SS) * HD;
    const __nv_bfloat16* vhp = vh + ((size_t)(b*NKV + hkv) * SS) * HD;
    const __nv_bfloat16* vlp = vl + ((size_t)(b*NKV + hkv) * SS) * HD;

    auto fill_kv = [&](int stage, int kb) {
        const int k0 = kb * 64;
        const uint32_t dst = sb + KV_OFF + stage * KVSTAGE;
        #pragma unroll
        for (int i = 0; i < 4; i++) {
            int lin = tid + i*256;
            int r   = lin >> 4;
            int ch  = lin & 15;
            size_t g = (size_t)(k0 + r)*HD + ch*8;
            uint32_t so = r*FST + ch*16;
            cp16(dst +           so, khp + g);
            cp16(dst +   KVSPL + so, klp + g);
            cp16(dst + 2*KVSPL + so, vhp + g);
            cp16(dst + 3*KVSPL + so, vlp + g);
        }
        asm volatile("cp.async.commit_group;" ::: "memory");
    };

    // group 0: Q (resident) + KV tile 0
    #pragma unroll
    for (int i = 0; i < 8; i++) {
        int lin = tid + i*256;
        int r   = lin >> 4;
        int ch  = lin & 15;
        cp16(sb + QH_OFF + r*FST + ch*16, qhp + (size_t)r*HD + ch*8);
        cp16(sb + QL_OFF + r*FST + ch*16, qlp + (size_t)r*HD + ch*8);
    }
    {
        const int k0 = 0;
        const uint32_t dst = sb + KV_OFF;
        #pragma unroll
        for (int i = 0; i < 4; i++) {
            int lin = tid + i*256;
            int r   = lin >> 4;
            int ch  = lin & 15;
            size_t g = (size_t)(k0 + r)*HD + ch*8;
            uint32_t so = r*FST + ch*16;
            cp16(dst +           so, khp + g);
            cp16(dst +   KVSPL + so, klp + g);
            cp16(dst + 2*KVSPL + so, vhp + g);
            cp16(dst + 3*KVSPL + so, vlp + g);
        }
        asm volatile("cp.async.commit_group;" ::: "memory");
    }

    const int nkb = 2*qb + 2;
    fill_kv(1, 1);   // nkb >= 2 always

    const int l8 = lane & 7;
    const int rA = ((lane >> 3) & 1) * 8 + l8;
    const int cA = ((lane >> 4) & 1) * 16;
    const int rB = ((lane >> 4) & 1) * 8 + l8;
    const int cB = ((lane >> 3) & 1) * 16;
    const int lr = lane >> 2;
    const int l4 = lane & 3;

    float O[16][4];
    #pragma unroll
    for (int j = 0; j < 16; j++)
        #pragma unroll
        for (int r = 0; r < 4; r++) O[j][r] = 0.f;
    float m0v = -1e30f, m1v = -1e30f, l0v = 0.f, l1v = 0.f;

    for (int kb = 0; kb < nkb; ++kb) {
        if (kb + 1 < nkb) asm volatile("cp.async.wait_group 1;" ::: "memory");
        else              asm volatile("cp.async.wait_group 0;" ::: "memory");
        __syncthreads();

        const uint32_t kvb = sb + KV_OFF + (kb & 1) * KVSTAGE;
        const int k0 = kb * 64;

        float S[8][4];
        #pragma unroll
        for (int j = 0; j < 8; j++)
            #pragma unroll
            for (int r = 0; r < 4; r++) S[j][r] = 0.f;

        #pragma unroll
        for (int kc = 0; kc < 8; kc++) {
            uint32_t qa_h[4], qa_l[4];
            uint32_t qaddr = sb + QH_OFF + (uint32_t)(mrow + rA)*FST + kc*32 + cA;
            LDSM4(qa_h, qaddr);
            LDSM4(qa_l, qaddr + (QL_OFF - QH_OFF));
            #pragma unroll
            for (int ng = 0; ng < 4; ng++) {
                uint32_t kaddr = kvb + (uint32_t)(ng*16 + rB)*FST + kc*32 + cB;
                uint32_t bh4[4], bl4[4];
                LDSM4(bh4, kaddr);
                LDSM4(bl4, kaddr + KVSPL);
                MMA_BF16(S[2*ng],   qa_h, bh4[0], bh4[1]);
                MMA_BF16(S[2*ng],   qa_h, bl4[0], bl4[1]);
                MMA_BF16(S[2*ng],   qa_l, bh4[0], bh4[1]);
                MMA_BF16(S[2*ng+1], qa_h, bh4[2], bh4[3]);
                MMA_BF16(S[2*ng+1], qa_h, bl4[2], bl4[3]);
                MMA_BF16(S[2*ng+1], qa_l, bh4[2], bh4[3]);
            }
        }

        if (kb >= 2*qb) {
            int row0 = q0 + mrow + lr;
            int row1 = row0 + 8;
            #pragma unroll
            for (int j = 0; j < 8; j++) {
                int c0 = k0 + 8*j + 2*l4;
                if (c0     > row0) S[j][0] = -1e30f;
                if (c0 + 1 > row0) S[j][1] = -1e30f;
                if (c0     > row1) S[j][2] = -1e30f;
                if (c0 + 1 > row1) S[j][3] = -1e30f;
            }
        }

        {
            float mx = -1e30f;
            #pragma unroll
            for (int j = 0; j < 8; j++) mx = fmaxf(mx, fmaxf(S[j][0], S[j][1]));
            mx = fmaxf(mx, __shfl_xor_sync(0xffffffffu, mx, 1));
            mx = fmaxf(mx, __shfl_xor_sync(0xffffffffu, mx, 2));
            float mn = fmaxf(m0v, mx);
            float corr = ex2f(m0v - mn);
            m0v = mn;
            float rs = 0.f;
            #pragma unroll
            for (int j = 0; j < 8; j++) {
                S[j][0] = ex2f(S[j][0] - mn);
                S[j][1] = ex2f(S[j][1] - mn);
                rs += S[j][0] + S[j][1];
            }
            rs += __shfl_xor_sync(0xffffffffu, rs, 1);
            rs += __shfl_xor_sync(0xffffffffu, rs, 2);
            l0v = l0v * corr + rs;
            #pragma unroll
            for (int j = 0; j < 16; j++) { O[j][0] *= corr; O[j][1] *= corr; }
        }
        {
            float mx = -1e30f;
            #pragma unroll
            for (int j = 0; j < 8; j++) mx = fmaxf(mx, fmaxf(S[j][2], S[j][3]));
            mx = fmaxf(mx, __shfl_xor_sync(0xffffffffu, mx, 1));
            mx = fmaxf(mx, __shfl_xor_sync(0xffffffffu, mx, 2));
            float mn = fmaxf(m1v, mx);
            float corr = ex2f(m1v - mn);
            m1v = mn;
            float rs = 0.f;
            #pragma unroll
            for (int j = 0; j < 8; j++) {
                S[j][2] = ex2f(S[j][2] - mn);
                S[j][3] = ex2f(S[j][3] - mn);
                rs += S[j][2] + S[j][3];
            }
            rs += __shfl_xor_sync(0xffffffffu, rs, 1);
            rs += __shfl_xor_sync(0xffffffffu, rs, 2);
            l1v = l1v * corr + rs;
            #pragma unroll
            for (int j = 0; j < 16; j++) { O[j][2] *= corr; O[j][3] *= corr; }
        }

        #pragma unroll
        for (int t = 0; t < 4; t++) {
            uint32_t Ahf[4], Alf[4];
            Ahf[0] = cvt2(S[2*t][1],   S[2*t][0]);
            Ahf[1] = cvt2(S[2*t][3],   S[2*t][2]);
            Ahf[2] = cvt2(S[2*t+1][1], S[2*t+1][0]);
            Ahf[3] = cvt2(S[2*t+1][3], S[2*t+1][2]);
            Alf[0] = cvt2(S[2*t][1]   - hi_f(Ahf[0]), S[2*t][0]   - lo_f(Ahf[0]));
            Alf[1] = cvt2(S[2*t][3]   - hi_f(Ahf[1]), S[2*t][2]   - lo_f(Ahf[1]));
            Alf[2] = cvt2(S[2*t+1][1] - hi_f(Ahf[2]), S[2*t+1][0] - lo_f(Ahf[2]));
            Alf[3] = cvt2(S[2*t+1][3] - hi_f(Ahf[3]), S[2*t+1][2] - lo_f(Ahf[3]));
            #pragma unroll
            for (int dg = 0; dg < 8; dg++) {
                uint32_t vaddr = kvb + 2*KVSPL + (uint32_t)(t*16 + rA)*FST + dg*32 + cA;
                uint32_t vhf[4], vlf[4];
                LDSM4T(vhf, vaddr);
                LDSM4T(vlf, vaddr + KVSPL);
                MMA_BF16(O[2*dg],   Ahf, vhf[0], vhf[1]);
                MMA_BF16(O[2*dg],   Ahf, vlf[0], vlf[1]);
                MMA_BF16(O[2*dg],   Alf, vhf[0], vhf[1]);
                MMA_BF16(O[2*dg+1], Ahf, vhf[2], vhf[3]);
                MMA_BF16(O[2*dg+1], Ahf, vlf[2], vlf[3]);
                MMA_BF16(O[2*dg+1], Alf, vhf[2], vhf[3]);
            }
        }

        __syncthreads();   // all warps done reading stage kb&1
        if (kb + 2 < nkb) fill_kv(kb & 1, kb + 2);
    }

    float inv0 = 1.0f / l0v;
    float inv1 = 1.0f / l1v;
    int row0 = q0 + mrow + lr;
    size_t base0 = (size_t)(b*SS + row0) * DD + h*HD;
    size_t base1 = base0 + (size_t)8 * DD;
    #pragma unroll
    for (int j = 0; j < 16; j++) {
        float a0 = O[j][0]*inv0, a1 = O[j][1]*inv0;
        float b0 = O[j][2]*inv1, b1 = O[j][3]*inv1;
        uint32_t h0 = cvt2(a1, a0);
        uint32_t l0 = cvt2(a1 - hi_f(h0), a0 - lo_f(h0));
        uint32_t h1 = cvt2(b1, b0);
        uint32_t l1 = cvt2(b1 - hi_f(h1), b0 - lo_f(h1));
        *(uint32_t*)(Yh + base0 + 8*j + 2*l4) = h0;
        *(uint32_t*)(Yl + base0 + 8*j + 2*l4) = l0;
        *(uint32_t*)(Yh + base1 + 8*j + 2*l4) = h1;
        *(uint32_t*)(Yl + base1 + 8*j + 2*l4) = l1;
    }
}

// ---------------- launch ----------------------------------------------------
extern "C" void kernel_launch(void* const* d_in, const int* in_sizes, int n_in,
                              void* d_out, int out_size)
{
    const float* x     = (const float*)d_in[0];
    const float* freqs = (const float*)d_in[1];
    const float* wqkv  = (const float*)d_in[2];
    const float* wo    = (const float*)d_in[3];
    const float* qw    = (const float*)d_in[4];
    const float* kw    = (const float*)d_in[5];
    float* out = (float*)d_out;

    float *p_qkv;
    __half *p_xh, *p_wqh;
    __nv_bfloat16 *p_woh, *p_wol, *p_yh, *p_yl;
    __nv_bfloat16 *p_qh, *p_ql, *p_kh, *p_kl, *p_vh, *p_vl;
    cudaGetSymbolAddress((void**)&p_qkv, g_qkv);
    cudaGetSymbolAddress((void**)&p_xh,  g_xh);
    cudaGetSymbolAddress((void**)&p_wqh, g_wqh);
    cudaGetSymbolAddress((void**)&p_woh, g_woh);
    cudaGetSymbolAddress((void**)&p_wol, g_wol);
    cudaGetSymbolAddress((void**)&p_yh,  g_yh);
    cudaGetSymbolAddress((void**)&p_yl,  g_yl);
    cudaGetSymbolAddress((void**)&p_qh,  g_qh);
    cudaGetSymbolAddress((void**)&p_ql,  g_ql);
    cudaGetSymbolAddress((void**)&p_kh,  g_kh);
    cudaGetSymbolAddress((void**)&p_kl,  g_kl);
    cudaGetSymbolAddress((void**)&p_vh,  g_vh);
    cudaGetSymbolAddress((void**)&p_vl,  g_vl);

    cudaFuncSetAttribute(gemm_f16,
                         cudaFuncAttributeMaxDynamicSharedMemorySize, HGSMEM);
    cudaFuncSetAttribute(gemm_mma3,
                         cudaFuncAttributeMaxDynamicSharedMemorySize, GSMEM);
    cudaFuncSetAttribute(flash_mma,
                         cudaFuncAttributeMaxDynamicSharedMemorySize, FLASH_SMEM);

    const int n4_x  = BB*SS*DD / 4;
    const int n4_wq = QKVE*DD  / 4;
    const int n4_wo = DD*DD    / 4;

    // 0) converts
    to_half<<<n4_x /256, 256>>>((const float4*)x,    (uint2*)p_xh,  n4_x);
    to_half<<<n4_wq/256, 256>>>((const float4*)wqkv, (uint2*)p_wqh, n4_wq);
    split_bf16<<<n4_wo/256, 256>>>((const float4*)wo, (uint2*)p_woh, (uint2*)p_wol, n4_wo);

    // 1) QKV projection (fp16 1-pass, 3-stage pipeline)
    gemm_f16<<<dim3(QKVE/128, (BB*SS)/128), 256, HGSMEM>>>(
        p_xh, p_wqh, p_qkv, QKVE, DD);

    // 2) RMSNorm + RoPE + bf16 hi/lo split
    norm_split<<<dim3(SS/8, EHEADS, BB), 256>>>(p_qkv, freqs, qw, kw,
                                                p_qh, p_ql, p_kh, p_kl, p_vh, p_vl);

    // 3) Flash attention (bf16x3, double-buffered K/V)
    flash_mma<<<dim3(SS/128, NH, BB), 256, FLASH_SMEM>>>(
        p_qh, p_ql, p_kh, p_kl, p_vh, p_vl, p_yh, p_yl);

    // 4) Output projection (bf16x3)
    gemm_mma3<<<dim3(DD/128, (BB*SS)/128), 256, GSMEM>>>(
        p_yh, p_yl, p_woh, p_wol, out, DD, NH*HD);
}

// round 13
// speedup vs baseline: 3.1132x; 1.0570x over previous
#include <cuda_runtime.h>
#include <cuda_fp16.h>
#include <cuda_bf16.h>
#include <math.h>
#include <stdint.h>

// Problem constants
#define BB   2
#define SS   2048
#define DD   2048
#define NH   16
#define NKV  4
#define HD   128
#define EHEADS (NH + 2*NKV)          // 24
#define QKVE (EHEADS * HD)           // 3072

// ---------------- scratch (device globals; no allocation allowed) ----------
// fp16 operands (QKV projection only)
__device__ __align__(16) __half g_xh [(size_t)BB*SS*DD];
__device__ __align__(16) __half g_wqh[(size_t)QKVE*DD];
// bf16 split operands (out projection + flash)
__device__ __align__(16) __nv_bfloat16 g_woh[(size_t)DD*DD];
__device__ __align__(16) __nv_bfloat16 g_wol[(size_t)DD*DD];
__device__ __align__(16) __nv_bfloat16 g_yh [(size_t)BB*SS*DD];
__device__ __align__(16) __nv_bfloat16 g_yl [(size_t)BB*SS*DD];
__device__ __align__(16) __nv_bfloat16 g_qh [(size_t)BB*NH *SS*HD];
__device__ __align__(16) __nv_bfloat16 g_ql [(size_t)BB*NH *SS*HD];
__device__ __align__(16) __nv_bfloat16 g_kh [(size_t)BB*NKV*SS*HD];
__device__ __align__(16) __nv_bfloat16 g_kl [(size_t)BB*NKV*SS*HD];
__device__ __align__(16) __nv_bfloat16 g_vh [(size_t)BB*NKV*SS*HD];
__device__ __align__(16) __nv_bfloat16 g_vl [(size_t)BB*NKV*SS*HD];

// ---------------- helpers ----------------------------------------------------
__device__ __forceinline__ float ex2f(float x) {
    float y;
    asm("ex2.approx.ftz.f32 %0, %1;" : "=f"(y) : "f"(x));
    return y;
}
__device__ __forceinline__ uint32_t s2u(const void* p) {
    uint32_t r;
    asm("{ .reg .u64 t; cvta.to.shared.u64 t, %1; cvt.u32.u64 %0, t; }" : "=r"(r) : "l"(p));
    return r;
}
__device__ __forceinline__ void cp16(uint32_t dst, const void* src) {
    asm volatile("cp.async.cg.shared.global [%0], [%1], 16;" :: "r"(dst), "l"(src));
}
__device__ __forceinline__ uint32_t cvt2(float hi, float lo) {
    uint32_t r;
    asm("cvt.rn.bf16x2.f32 %0, %1, %2;" : "=r"(r) : "f"(hi), "f"(lo));
    return r;
}
__device__ __forceinline__ float lo_f(uint32_t u) { return __uint_as_float(u << 16); }
__device__ __forceinline__ float hi_f(uint32_t u) { return __uint_as_float(u & 0xffff0000u); }
__device__ __forceinline__ uint32_t pack_h2(float lo, float hi) {
    __half2 h = __floats2half2_rn(lo, hi);
    return *reinterpret_cast<uint32_t*>(&h);
}

#define LDSM4(r, addr) \
    asm volatile("ldmatrix.sync.aligned.m8n8.x4.shared.b16 {%0,%1,%2,%3}, [%4];" \
        : "=r"((r)[0]), "=r"((r)[1]), "=r"((r)[2]), "=r"((r)[3]) : "r"(addr))
#define LDSM4T(r, addr) \
    asm volatile("ldmatrix.sync.aligned.m8n8.x4.trans.shared.b16 {%0,%1,%2,%3}, [%4];" \
        : "=r"((r)[0]), "=r"((r)[1]), "=r"((r)[2]), "=r"((r)[3]) : "r"(addr))

#define MMA_BF16(d, a, b0v, b1v) \
    asm volatile("mma.sync.aligned.m16n8k16.row.col.f32.bf16.bf16.f32 " \
        "{%0,%1,%2,%3}, {%4,%5,%6,%7}, {%8,%9}, {%0,%1,%2,%3};" \
        : "+f"((d)[0]), "+f"((d)[1]), "+f"((d)[2]), "+f"((d)[3]) \
        : "r"((a)[0]), "r"((a)[1]), "r"((a)[2]), "r"((a)[3]), "r"(b0v), "r"(b1v))
#define MMA_F16(d, a, b0v, b1v) \
    asm volatile("mma.sync.aligned.m16n8k16.row.col.f32.f16.f16.f32 " \
        "{%0,%1,%2,%3}, {%4,%5,%6,%7}, {%8,%9}, {%0,%1,%2,%3};" \
        : "+f"((d)[0]), "+f"((d)[1]), "+f"((d)[2]), "+f"((d)[3]) \
        : "r"((a)[0]), "r"((a)[1]), "r"((a)[2]), "r"((a)[3]), "r"(b0v), "r"(b1v))

// ---------------- converters --------------------------------------------------
__global__ void __launch_bounds__(256) to_half(const float4* __restrict__ src,
                                               uint2* __restrict__ dst, int n4)
{
    int i = blockIdx.x * 256 + threadIdx.x;
    if (i >= n4) return;
    float4 v = src[i];
    dst[i] = make_uint2(pack_h2(v.x, v.y), pack_h2(v.z, v.w));
}

__global__ void __launch_bounds__(256) split_bf16(const float4* __restrict__ src,
                                                  uint2* __restrict__ hi,
                                                  uint2* __restrict__ lo,
                                                  int n4)
{
    int i = blockIdx.x * 256 + threadIdx.x;
    if (i >= n4) return;
    float4 v = src[i];
    uint32_t h01 = cvt2(v.y, v.x);
    uint32_t h23 = cvt2(v.w, v.z);
    uint32_t l01 = cvt2(v.y - hi_f(h01), v.x - lo_f(h01));
    uint32_t l23 = cvt2(v.w - hi_f(h23), v.z - lo_f(h23));
    hi[i] = make_uint2(h01, h23);
    lo[i] = make_uint2(l01, l23);
}

// ---------------- fused QKV GEMM + RMSNorm + RoPE + bf16 split ---------------
// fp16 1-pass, 3-stage pipeline, 1 sync/chunk. CTA N-block (128) == one head.
#define QSCALE 0.12751943f   // (1/sqrt(128)) * log2(e)
#define HSTG   10240
#define HSTAGE (2*HSTG)
#define HGSMEM (3*HSTAGE)            // 61440

__global__ void __launch_bounds__(256) gemm_qkv(
    const __half* __restrict__ Ah, const __half* __restrict__ Bh,
    const float* __restrict__ freqs,
    const float* __restrict__ qw, const float* __restrict__ kw,
    __nv_bfloat16* __restrict__ qh, __nv_bfloat16* __restrict__ ql,
    __nv_bfloat16* __restrict__ kh, __nv_bfloat16* __restrict__ kl,
    __nv_bfloat16* __restrict__ vh, __nv_bfloat16* __restrict__ vl)
{
    const int K = DD;
    extern __shared__ __align__(16) char smg[];
    const uint32_t sb = s2u(smg);
    const int tid  = threadIdx.x;
    const int lane = tid & 31;
    const int wid  = tid >> 5;
    const int wr   = wid >> 2;
    const int wc   = wid & 3;
    const int h    = blockIdx.x;          // head index (N-block == head)
    const int bm   = blockIdx.y << 7;
    const int bn   = h << 7;
    const int nk   = K >> 5;

    float acc[4][4][4];
    #pragma unroll
    for (int i = 0; i < 4; i++)
        #pragma unroll
        for (int j = 0; j < 4; j++)
            #pragma unroll
            for (int r = 0; r < 4; r++) acc[i][j][r] = 0.f;

    const int l8     = lane & 7;
    const int rowA   = ((lane >> 3) & 1) * 8 + l8;
    const int kbyteA = ((lane >> 4) & 1) * 16;
    const int rowB   = ((lane >> 4) & 1) * 8 + l8;
    const int byteB  = ((lane >> 3) & 1) * 16;

    auto fill = [&](int s, int kc) {
        const int k0 = kc << 5;
        const uint32_t dst = sb + s * HSTAGE;
        #pragma unroll
        for (int i = 0; i < 2; i++) {
            int lin = tid + i * 256;
            int row = lin >> 2;
            int ch  = lin & 3;
            uint32_t so = row * 80 + ch * 16;
            cp16(dst +        so, Ah + (size_t)(bm + row) * K + k0 + ch * 8);
            cp16(dst + HSTG + so, Bh + (size_t)(bn + row) * K + k0 + ch * 8);
        }
        asm volatile("cp.async.commit_group;" ::: "memory");
    };

    fill(0, 0);
    fill(1, 1);

    for (int t = 0; t < nk; ++t) {
        if (t + 1 < nk) asm volatile("cp.async.wait_group 1;" ::: "memory");
        else            asm volatile("cp.async.wait_group 0;" ::: "memory");
        __syncthreads();

        if (t + 2 < nk) fill((t + 2) % 3, t + 2);

        const uint32_t st = sb + (t % 3) * HSTAGE;
        #pragma unroll
        for (int kh2 = 0; kh2 < 2; kh2++) {
            uint32_t ah[4][4];
            #pragma unroll
            for (int mi = 0; mi < 4; mi++) {
                uint32_t aaddr = st + (uint32_t)(wr*64 + mi*16 + rowA) * 80
                               + kh2*32 + kbyteA;
                LDSM4(ah[mi], aaddr);
            }
            #pragma unroll
            for (int np = 0; np < 2; np++) {
                uint32_t baddr = st + HSTG + (uint32_t)(wc*32 + np*16 + rowB) * 80
                               + kh2*32 + byteB;
                uint32_t bh4[4];
                LDSM4(bh4, baddr);
                #pragma unroll
                for (int mi = 0; mi < 4; mi++) {
                    MMA_F16(acc[mi][2*np],   ah[mi], bh4[0], bh4[1]);
                    MMA_F16(acc[mi][2*np+1], ah[mi], bh4[2], bh4[3]);
                }
            }
        }
    }

    // ---- fused epilogue: rmsnorm + rope + bf16 split ----
    __syncthreads();                      // stage smem now reusable
    float* red = (float*)smg;             // [128 rows][4 wc]
    const int er = lane >> 2;
    const int ec = (lane & 3) * 2;
    const bool isq = (h < NH);
    const bool isv = (h >= NH + NKV);

    // per-row sum of squares (needed for q/k heads only, cheap anyway)
    #pragma unroll
    for (int mi = 0; mi < 4; mi++) {
        float s0 = 0.f, s1 = 0.f;
        #pragma unroll
        for (int nn = 0; nn < 4; nn++) {
            s0 += acc[mi][nn][0]*acc[mi][nn][0] + acc[mi][nn][1]*acc[mi][nn][1];
            s1 += acc[mi][nn][2]*acc[mi][nn][2] + acc[mi][nn][3]*acc[mi][nn][3];
        }
        s0 += __shfl_xor_sync(0xffffffffu, s0, 1);
        s0 += __shfl_xor_sync(0xffffffffu, s0, 2);
        s1 += __shfl_xor_sync(0xffffffffu, s1, 1);
        s1 += __shfl_xor_sync(0xffffffffu, s1, 2);
        if ((lane & 3) == 0) {
            red[(wr*64 + mi*16 + er)     * 4 + wc] = s0;
            red[(wr*64 + mi*16 + er + 8) * 4 + wc] = s1;
        }
    }
    __syncthreads();

    const float* wn = isq ? qw : kw;
    const float fold = isq ? QSCALE : 1.0f;

    #pragma unroll
    for (int mi = 0; mi < 4; mi++) {
        #pragma unroll
        for (int half = 0; half < 2; half++) {
            const int row = wr*64 + mi*16 + er + half*8;
            const int n   = bm + row;
            const int b   = n >> 11;
            const int s   = n & 2047;
            float inv = 1.0f;
            if (!isv) {
                float ssq = red[row*4+0] + red[row*4+1] + red[row*4+2] + red[row*4+3];
                inv = rsqrtf(ssq * (1.0f / HD) + 1e-6f) * fold;
            }
            size_t drow;
            __nv_bfloat16 *dh, *dl;
            if (isq)      { drow = (size_t)(b*NH  + h)          * SS + s; dh = qh; dl = ql; }
            else if (!isv){ drow = (size_t)(b*NKV + h - NH)     * SS + s; dh = kh; dl = kl; }
            else          { drow = (size_t)(b*NKV + h - NH - NKV)* SS + s; dh = vh; dl = vl; }

            #pragma unroll
            for (int nn = 0; nn < 4; nn++) {
                const int col = wc*32 + nn*8 + ec;
                float v0 = acc[mi][nn][half*2];
                float v1 = acc[mi][nn][half*2+1];
                float o0, o1;
                if (!isv) {
                    float2 wv = *(const float2*)(wn + col);
                    float2 f  = *(const float2*)(freqs + (size_t)s*128 + col);
                    float x0 = v0 * inv * wv.x;
                    float x1 = v1 * inv * wv.y;
                    o0 = x0*f.x - x1*f.y;
                    o1 = x1*f.x + x0*f.y;
                } else {
                    o0 = v0; o1 = v1;
                }
                uint32_t hp = cvt2(o1, o0);
                uint32_t lp = cvt2(o1 - hi_f(hp), o0 - lo_f(hp));
                *(uint32_t*)(dh + drow*HD + col) = hp;
                *(uint32_t*)(dl + drow*HD + col) = lp;
            }
        }
    }
}

// ---------------- bf16x3 GEMM (2-stage, unchanged) ---------------------------
#define STG   10240
#define STAGE (4*STG)
#define GSMEM (2*STAGE)              // 81920

__global__ void __launch_bounds__(256) gemm_mma3(
    const __nv_bfloat16* __restrict__ Ah, const __nv_bfloat16* __restrict__ Al,
    const __nv_bfloat16* __restrict__ Bh, const __nv_bfloat16* __restrict__ Bl,
    float* __restrict__ C, int N, int K)
{
    extern __shared__ __align__(16) char smg[];
    const uint32_t sb = s2u(smg);
    const int tid  = threadIdx.x;
    const int lane = tid & 31;
    const int wid  = tid >> 5;
    const int wr   = wid >> 2;
    const int wc   = wid & 3;
    const int bm   = blockIdx.y << 7;
    const int bn   = blockIdx.x << 7;
    const int nk   = K >> 5;

    float acc[4][4][4];
    #pragma unroll
    for (int i = 0; i < 4; i++)
        #pragma unroll
        for (int j = 0; j < 4; j++)
            #pragma unroll
            for (int r = 0; r < 4; r++) acc[i][j][r] = 0.f;

    const int l8     = lane & 7;
    const int rowA   = ((lane >> 3) & 1) * 8 + l8;
    const int kbyteA = ((lane >> 4) & 1) * 16;
    const int rowB   = ((lane >> 4) & 1) * 8 + l8;
    const int byteB  = ((lane >> 3) & 1) * 16;

    auto fill = [&](int s, int kc) {
        const int k0 = kc << 5;
        const uint32_t dst = sb + s * STAGE;
        #pragma unroll
        for (int i = 0; i < 2; i++) {
            int lin = tid + i * 256;
            int row = lin >> 2;
            int ch  = lin & 3;
            uint32_t so = row * 80 + ch * 16;
            size_t ga = (size_t)(bm + row) * K + k0 + ch * 8;
            size_t gb = (size_t)(bn + row) * K + k0 + ch * 8;
            cp16(dst +           so, Ah + ga);
            cp16(dst + STG     + so, Al + ga);
            cp16(dst + 2*STG   + so, Bh + gb);
            cp16(dst + 3*STG   + so, Bl + gb);
        }
    };

    fill(0, 0);
    asm volatile("cp.async.commit_group;" ::: "memory");

    for (int t = 0; t < nk; ++t) {
        if (t + 1 < nk) {
            fill((t + 1) & 1, t + 1);
            asm volatile("cp.async.commit_group;" ::: "memory");
            asm volatile("cp.async.wait_group 1;" ::: "memory");
        } else {
            asm volatile("cp.async.wait_group 0;" ::: "memory");
        }
        __syncthreads();

        const uint32_t st = sb + (t & 1) * STAGE;
        #pragma unroll
        for (int kh = 0; kh < 2; kh++) {
            uint32_t ah[4][4], al[4][4];
            #pragma unroll
            for (int mi = 0; mi < 4; mi++) {
                uint32_t aaddr = st + (uint32_t)(wr*64 + mi*16 + rowA) * 80
                               + kh*32 + kbyteA;
                LDSM4(ah[mi], aaddr);
                LDSM4(al[mi], aaddr + STG);
            }
            #pragma unroll
            for (int np = 0; np < 2; np++) {
                uint32_t baddr = st + 2*STG + (uint32_t)(wc*32 + np*16 + rowB) * 80
                               + kh*32 + byteB;
                uint32_t bh[4], bl[4];
                LDSM4(bh, baddr);
                LDSM4(bl, baddr + STG);
                #pragma unroll
                for (int mi = 0; mi < 4; mi++) {
                    MMA_BF16(acc[mi][2*np],   ah[mi], bh[0], bh[1]);
                    MMA_BF16(acc[mi][2*np],   ah[mi], bl[0], bl[1]);
                    MMA_BF16(acc[mi][2*np],   al[mi], bh[0], bh[1]);
                    MMA_BF16(acc[mi][2*np+1], ah[mi], bh[2], bh[3]);
                    MMA_BF16(acc[mi][2*np+1], ah[mi], bl[2], bl[3]);
                    MMA_BF16(acc[mi][2*np+1], al[mi], bh[2], bh[3]);
                }
            }
        }
        __syncthreads();
    }

    const int er = lane >> 2;
    const int ec = (lane & 3) * 2;
    #pragma unroll
    for (int mi = 0; mi < 4; mi++) {
        #pragma unroll
        for (int nn = 0; nn < 4; nn++) {
            float* cp0 = C + (size_t)(bm + wr*64 + mi*16 + er) * N
                           + bn + wc*32 + nn*8 + ec;
            *(float2*)cp0         = make_float2(acc[mi][nn][0], acc[mi][nn][1]);
            *(float2*)(cp0 + 8*N) = make_float2(acc[mi][nn][2], acc[mi][nn][3]);
        }
    }
}

// ---------------- Flash attention (bf16x3), BM=64, 4 warps, 2 CTAs/SM --------
#define FST 272
#define Q_OFF  0
#define QL_OFF (64*FST)                 // 17408
#define KH_OFF (2*64*FST)               // 34816
#define KL_OFF (3*64*FST)
#define VH_OFF (4*64*FST)
#define VL_OFF (5*64*FST)
#define FLASH_SMEM (6*64*FST)           // 104448

__global__ void __launch_bounds__(128) flash_mma(
    const __nv_bfloat16* __restrict__ qh, const __nv_bfloat16* __restrict__ ql,
    const __nv_bfloat16* __restrict__ kh, const __nv_bfloat16* __restrict__ kl,
    const __nv_bfloat16* __restrict__ vh, const __nv_bfloat16* __restrict__ vl,
    __nv_bfloat16* __restrict__ Yh, __nv_bfloat16* __restrict__ Yl)
{
    extern __shared__ __align__(16) char smf[];
    const uint32_t sb = s2u(smf);
    const int tid  = threadIdx.x;
    const int lane = tid & 31;
    const int wid  = tid >> 5;            // 0..3
    const int qb   = gridDim.x - 1 - blockIdx.x;
    const int h    = blockIdx.y;
    const int b    = blockIdx.z;
    const int q0   = qb * 64;
    const int hkv  = h >> 2;
    const int mrow = wid * 16;

    const __nv_bfloat16* qhp = qh + ((size_t)(b*NH  + h  ) * SS + q0) * HD;
    const __nv_bfloat16* qlp = ql + ((size_t)(b*NH  + h  ) * SS + q0) * HD;
    const __nv_bfloat16* khp = kh + ((size_t)(b*NKV + hkv) * SS) * HD;
    const __nv_bfloat16* klp = kl + ((size_t)(b*NKV + hkv) * SS) * HD;
    const __nv_bfloat16* vhp = vh + ((size_t)(b*NKV + hkv) * SS) * HD;
    const __nv_bfloat16* vlp = vl + ((size_t)(b*NKV + hkv) * SS) * HD;

    // Q tile (resident): 64 rows x 16 chunks x {hi,lo}
    #pragma unroll
    for (int i = 0; i < 8; i++) {
        int lin = tid + i*128;
        int r   = lin >> 4;
        int ch  = lin & 15;
        cp16(sb + Q_OFF  + r*FST + ch*16, qhp + (size_t)r*HD + ch*8);
        cp16(sb + QL_OFF + r*FST + ch*16, qlp + (size_t)r*HD + ch*8);
    }
    asm volatile("cp.async.commit_group;" ::: "memory");

    const int l8 = lane & 7;
    const int rA = ((lane >> 3) & 1) * 8 + l8;
    const int cA = ((lane >> 4) & 1) * 16;
    const int rB = ((lane >> 4) & 1) * 8 + l8;
    const int cB = ((lane >> 3) & 1) * 16;
    const int lr = lane >> 2;
    const int l4 = lane & 3;

    float O[16][4];
    #pragma unroll
    for (int j = 0; j < 16; j++)
        #pragma unroll
        for (int r = 0; r < 4; r++) O[j][r] = 0.f;
    float m0v = -1e30f, m1v = -1e30f, l0v = 0.f, l1v = 0.f;

    const int nkb = qb + 1;
    for (int kb = 0; kb < nkb; ++kb) {
        const int k0 = kb * 64;
        if (kb) __syncthreads();   // prev compute done before overwrite
        #pragma unroll
        for (int i = 0; i < 8; i++) {
            int lin = tid + i*128;
            int r   = lin >> 4;
            int ch  = lin & 15;
            size_t g = (size_t)(k0 + r)*HD + ch*8;
            uint32_t so = r*FST + ch*16;
            cp16(sb + KH_OFF + so, khp + g);
            cp16(sb + KL_OFF + so, klp + g);
            cp16(sb + VH_OFF + so, vhp + g);
            cp16(sb + VL_OFF + so, vlp + g);
        }
        asm volatile("cp.async.commit_group;" ::: "memory");
        asm volatile("cp.async.wait_group 0;" ::: "memory");
        __syncthreads();

        float S[8][4];
        #pragma unroll
        for (int j = 0; j < 8; j++)
            #pragma unroll
            for (int r = 0; r < 4; r++) S[j][r] = 0.f;

        #pragma unroll
        for (int kc = 0; kc < 8; kc++) {
            uint32_t qa_h[4], qa_l[4];
            uint32_t qaddr = sb + Q_OFF + (uint32_t)(mrow + rA)*FST + kc*32 + cA;
            LDSM4(qa_h, qaddr);
            LDSM4(qa_l, qaddr + QL_OFF);
            #pragma unroll
            for (int ng = 0; ng < 4; ng++) {
                uint32_t kaddr = sb + KH_OFF + (uint32_t)(ng*16 + rB)*FST + kc*32 + cB;
                uint32_t bh4[4], bl4[4];
                LDSM4(bh4, kaddr);
                LDSM4(bl4, kaddr + (KL_OFF - KH_OFF));
                MMA_BF16(S[2*ng],   qa_h, bh4[0], bh4[1]);
                MMA_BF16(S[2*ng],   qa_h, bl4[0], bl4[1]);
                MMA_BF16(S[2*ng],   qa_l, bh4[0], bh4[1]);
                MMA_BF16(S[2*ng+1], qa_h, bh4[2], bh4[3]);
                MMA_BF16(S[2*ng+1], qa_h, bl4[2], bl4[3]);
                MMA_BF16(S[2*ng+1], qa_l, bh4[2], bh4[3]);
            }
        }

        if (kb == qb) {
            int row0 = q0 + mrow + lr;
            int row1 = row0 + 8;
            #pragma unroll
            for (int j = 0; j < 8; j++) {
                int c0 = k0 + 8*j + 2*l4;
                if (c0     > row0) S[j][0] = -1e30f;
                if (c0 + 1 > row0) S[j][1] = -1e30f;
                if (c0     > row1) S[j][2] = -1e30f;
                if (c0 + 1 > row1) S[j][3] = -1e30f;
            }
        }

        {
            float mx = -1e30f;
            #pragma unroll
            for (int j = 0; j < 8; j++) mx = fmaxf(mx, fmaxf(S[j][0], S[j][1]));
            mx = fmaxf(mx, __shfl_xor_sync(0xffffffffu, mx, 1));
            mx = fmaxf(mx, __shfl_xor_sync(0xffffffffu, mx, 2));
            float mn = fmaxf(m0v, mx);
            float corr = ex2f(m0v - mn);
            m0v = mn;
            float rs = 0.f;
            #pragma unroll
            for (int j = 0; j < 8; j++) {
                S[j][0] = ex2f(S[j][0] - mn);
                S[j][1] = ex2f(S[j][1] - mn);
                rs += S[j][0] + S[j][1];
            }
            rs += __shfl_xor_sync(0xffffffffu, rs, 1);
            rs += __shfl_xor_sync(0xffffffffu, rs, 2);
            l0v = l0v * corr + rs;
            #pragma unroll
            for (int j = 0; j < 16; j++) { O[j][0] *= corr; O[j][1] *= corr; }
        }
        {
            float mx = -1e30f;
            #pragma unroll
            for (int j = 0; j < 8; j++) mx = fmaxf(mx, fmaxf(S[j][2], S[j][3]));
            mx = fmaxf(mx, __shfl_xor_sync(0xffffffffu, mx, 1));
            mx = fmaxf(mx, __shfl_xor_sync(0xffffffffu, mx, 2));
            float mn = fmaxf(m1v, mx);
            float corr = ex2f(m1v - mn);
            m1v = mn;
            float rs = 0.f;
            #pragma unroll
            for (int j = 0; j < 8; j++) {
                S[j][2] = ex2f(S[j][2] - mn);
                S[j][3] = ex2f(S[j][3] - mn);
                rs += S[j][2] + S[j][3];
            }
            rs += __shfl_xor_sync(0xffffffffu, rs, 1);
            rs += __shfl_xor_sync(0xffffffffu, rs, 2);
            l1v = l1v * corr + rs;
            #pragma unroll
            for (int j = 0; j < 16; j++) { O[j][2] *= corr; O[j][3] *= corr; }
        }

        #pragma unroll
        for (int t = 0; t < 4; t++) {
            uint32_t Ahf[4], Alf[4];
            Ahf[0] = cvt2(S[2*t][1],   S[2*t][0]);
            Ahf[1] = cvt2(S[2*t][3],   S[2*t][2]);
            Ahf[2] = cvt2(S[2*t+1][1], S[2*t+1][0]);
            Ahf[3] = cvt2(S[2*t+1][3], S[2*t+1][2]);
            Alf[0] = cvt2(S[2*t][1]   - hi_f(Ahf[0]), S[2*t][0]   - lo_f(Ahf[0]));
            Alf[1] = cvt2(S[2*t][3]   - hi_f(Ahf[1]), S[2*t][2]   - lo_f(Ahf[1]));
            Alf[2] = cvt2(S[2*t+1][1] - hi_f(Ahf[2]), S[2*t+1][0] - lo_f(Ahf[2]));
            Alf[3] = cvt2(S[2*t+1][3] - hi_f(Ahf[3]), S[2*t+1][2] - lo_f(Ahf[3]));
            #pragma unroll
            for (int dg = 0; dg < 8; dg++) {
                uint32_t vaddr = sb + VH_OFF + (uint32_t)(t*16 + rA)*FST + dg*32 + cA;
                uint32_t vhf[4], vlf[4];
                LDSM4T(vhf, vaddr);
                LDSM4T(vlf, vaddr + (VL_OFF - VH_OFF));
                MMA_BF16(O[2*dg],   Ahf, vhf[0], vhf[1]);
                MMA_BF16(O[2*dg],   Ahf, vlf[0], vlf[1]);
                MMA_BF16(O[2*dg],   Alf, vhf[0], vhf[1]);
                MMA_BF16(O[2*dg+1], Ahf, vhf[2], vhf[3]);
                MMA_BF16(O[2*dg+1], Ahf, vlf[2], vlf[3]);
                MMA_BF16(O[2*dg+1], Alf, vhf[2], vhf[3]);
            }
        }
    }

    float inv0 = 1.0f / l0v;
    float inv1 = 1.0f / l1v;
    int row0 = q0 + mrow + lr;
    size_t base0 = (size_t)(b*SS + row0) * DD + h*HD;
    size_t base1 = base0 + (size_t)8 * DD;
    #pragma unroll
    for (int j = 0; j < 16; j++) {
        float a0 = O[j][0]*inv0, a1 = O[j][1]*inv0;
        float b0 = O[j][2]*inv1, b1 = O[j][3]*inv1;
        uint32_t h0 = cvt2(a1, a0);
        uint32_t l0 = cvt2(a1 - hi_f(h0), a0 - lo_f(h0));
        uint32_t h1 = cvt2(b1, b0);
        uint32_t l1 = cvt2(b1 - hi_f(h1), b0 - lo_f(h1));
        *(uint32_t*)(Yh + base0 + 8*j + 2*l4) = h0;
        *(uint32_t*)(Yl + base0 + 8*j + 2*l4) = l0;
        *(uint32_t*)(Yh + base1 + 8*j + 2*l4) = h1;
        *(uint32_t*)(Yl + base1 + 8*j + 2*l4) = l1;
    }
}

// ---------------- launch ----------------------------------------------------
extern "C" void kernel_launch(void* const* d_in, const int* in_sizes, int n_in,
                              void* d_out, int out_size)
{
    const float* x     = (const float*)d_in[0];
    const float* freqs = (const float*)d_in[1];
    const float* wqkv  = (const float*)d_in[2];
    const float* wo    = (const float*)d_in[3];
    const float* qw    = (const float*)d_in[4];
    const float* kw    = (const float*)d_in[5];
    float* out = (float*)d_out;

    __half *p_xh, *p_wqh;
    __nv_bfloat16 *p_woh, *p_wol, *p_yh, *p_yl;
    __nv_bfloat16 *p_qh, *p_ql, *p_kh, *p_kl, *p_vh, *p_vl;
    cudaGetSymbolAddress((void**)&p_xh,  g_xh);
    cudaGetSymbolAddress((void**)&p_wqh, g_wqh);
    cudaGetSymbolAddress((void**)&p_woh, g_woh);
    cudaGetSymbolAddress((void**)&p_wol, g_wol);
    cudaGetSymbolAddress((void**)&p_yh,  g_yh);
    cudaGetSymbolAddress((void**)&p_yl,  g_yl);
    cudaGetSymbolAddress((void**)&p_qh,  g_qh);
    cudaGetSymbolAddress((void**)&p_ql,  g_ql);
    cudaGetSymbolAddress((void**)&p_kh,  g_kh);
    cudaGetSymbolAddress((void**)&p_kl,  g_kl);
    cudaGetSymbolAddress((void**)&p_vh,  g_vh);
    cudaGetSymbolAddress((void**)&p_vl,  g_vl);

    cudaFuncSetAttribute(gemm_qkv,
                         cudaFuncAttributeMaxDynamicSharedMemorySize, HGSMEM);
    cudaFuncSetAttribute(gemm_mma3,
                         cudaFuncAttributeMaxDynamicSharedMemorySize, GSMEM);
    cudaFuncSetAttribute(flash_mma,
                         cudaFuncAttributeMaxDynamicSharedMemorySize, FLASH_SMEM);

    const int n4_x  = BB*SS*DD / 4;
    const int n4_wq = QKVE*DD  / 4;
    const int n4_wo = DD*DD    / 4;

    // 0) converts
    to_half<<<n4_x /256, 256>>>((const float4*)x,    (uint2*)p_xh,  n4_x);
    to_half<<<n4_wq/256, 256>>>((const float4*)wqkv, (uint2*)p_wqh, n4_wq);
    split_bf16<<<n4_wo/256, 256>>>((const float4*)wo, (uint2*)p_woh, (uint2*)p_wol, n4_wo);

    // 1) fused QKV projection + RMSNorm + RoPE + bf16 split
    gemm_qkv<<<dim3(EHEADS, (BB*SS)/128), 256, HGSMEM>>>(
        p_xh, p_wqh, freqs, qw, kw,
        p_qh, p_ql, p_kh, p_kl, p_vh, p_vl);

    // 2) Flash attention (bf16x3, BM=64, 2 CTAs/SM)
    flash_mma<<<dim3(SS/64, NH, BB), 128, FLASH_SMEM>>>(
        p_qh, p_ql, p_kh, p_kl, p_vh, p_vl, p_yh, p_yl);

    // 3) Output projection (bf16x3)
    gemm_mma3<<<dim3(DD/128, (BB*SS)/128), 256, GSMEM>>>(
        p_yh, p_yl, p_woh, p_wol, out, DD, NH*HD);
}